// round 1
// baseline (speedup 1.0000x reference)
#include <cuda_runtime.h>
#include <math.h>

#define S_LEN 2048
#define DIM   2048
#define NH    32
#define NKV   8
#define HD    64
#define NREP  4           // NH / NKV
#define ATT_SCALE 0.125f  // 1/sqrt(64)

// ---------------- scratch (device globals; no allocation allowed) ----------
__device__ float g_q[S_LEN * NH * HD];     // 16 MB
__device__ float g_k[S_LEN * NKV * HD];    // 4 MB
__device__ float g_v[S_LEN * NKV * HD];    // 4 MB
__device__ float g_attn[S_LEN * NH * HD];  // 16 MB

// ---------------- SGEMM: C[M,N] = A[M,K] @ B[N,K]^T + bias[N] --------------
#define BM 64
#define BN 64
#define BK 16

__global__ void __launch_bounds__(256)
sgemm_bias(const float* __restrict__ A, const float* __restrict__ B,
           const float* __restrict__ bias, float* __restrict__ C,
           int M, int N, int K)
{
    __shared__ float As[BM][BK];       // natural layout
    __shared__ float Bs[BK][BN + 4];   // transposed, padded (68 floats/row, 16B-aligned)

    const int tid = threadIdx.x;
    const int m0 = blockIdx.y * BM;
    const int n0 = blockIdx.x * BN;
    const int tx = tid & 15;           // N micro index
    const int ty = tid >> 4;           // M micro index
    const int lr = tid >> 2;           // load row 0..63
    const int lc = (tid & 3) * 4;      // load col 0,4,8,12

    float acc[4][4];
#pragma unroll
    for (int i = 0; i < 4; i++)
#pragma unroll
        for (int j = 0; j < 4; j++) acc[i][j] = 0.f;

    for (int k0 = 0; k0 < K; k0 += BK) {
        float4 a4 = *(const float4*)&A[(m0 + lr) * K + k0 + lc];
        *(float4*)&As[lr][lc] = a4;
        float4 b4 = *(const float4*)&B[(n0 + lr) * K + k0 + lc];
        Bs[lc + 0][lr] = b4.x;
        Bs[lc + 1][lr] = b4.y;
        Bs[lc + 2][lr] = b4.z;
        Bs[lc + 3][lr] = b4.w;
        __syncthreads();

#pragma unroll
        for (int k = 0; k < BK; k++) {
            float ra[4];
#pragma unroll
            for (int i = 0; i < 4; i++) ra[i] = As[ty * 4 + i][k];
            float4 rb = *(const float4*)&Bs[k][tx * 4];
#pragma unroll
            for (int i = 0; i < 4; i++) {
                acc[i][0] += ra[i] * rb.x;
                acc[i][1] += ra[i] * rb.y;
                acc[i][2] += ra[i] * rb.z;
                acc[i][3] += ra[i] * rb.w;
            }
        }
        __syncthreads();
    }

#pragma unroll
    for (int i = 0; i < 4; i++) {
        int m = m0 + ty * 4 + i;
#pragma unroll
        for (int j = 0; j < 4; j++) {
            int n = n0 + tx * 4 + j;
            C[m * N + n] = acc[i][j] + bias[n];
        }
    }
}

// ---------------- RoPE (in place) ------------------------------------------
__global__ void rope_kernel(float* __restrict__ t, const float* __restrict__ rope,
                            int heads)
{
    int idx = blockIdx.x * blockDim.x + threadIdx.x;
    int total = S_LEN * heads * (HD / 2);
    if (idx >= total) return;
    int i = idx % (HD / 2);
    int h = (idx / (HD / 2)) % heads;
    int s = idx / (heads * (HD / 2));
    float c  = rope[s * HD + i];
    float sn = rope[s * HD + HD / 2 + i];
    float* p = t + (s * heads + h) * HD;
    float x1 = p[i], x2 = p[i + HD / 2];
    p[i]           = x1 * c  - x2 * sn;
    p[i + HD / 2]  = x1 * sn + x2 * c;
}

// ---------------- Flash attention with causal mask + sinks -----------------
#define BQ   64
#define BKV  64
#define PADR 68   // row pitch in floats (16B aligned: 68*4=272)

__global__ void __launch_bounds__(256)
attn_kernel(const float* __restrict__ Q, const float* __restrict__ K,
            const float* __restrict__ V, const float* __restrict__ sinks,
            float* __restrict__ O)
{
    extern __shared__ float sm[];
    float* q_s = sm;                    // BQ  * PADR
    float* k_s = q_s + BQ * PADR;       // BKV * PADR
    float* v_s = k_s + BKV * PADR;      // BKV * PADR
    float* p_s = v_s + BKV * PADR;      // BQ  * PADR

    const int h   = blockIdx.y;
    const int q0  = blockIdx.x * BQ;
    const int kvh = h / NREP;
    const int tid = threadIdx.x;
    const int r   = tid >> 2;           // query row within tile (0..63)
    const int c4  = tid & 3;            // 16-wide key/dim slice selector
    const int qg  = q0 + r;

    // load Q tile
    for (int idx = tid; idx < BQ * HD; idx += 256) {
        int row = idx >> 6, d = idx & 63;
        q_s[row * PADR + d] = Q[(q0 + row) * (NH * HD) + h * HD + d];
    }

    float acc[16];
#pragma unroll
    for (int j = 0; j < 16; j++) acc[j] = 0.f;
    float m = -INFINITY, l = 0.f;

    __syncthreads();

    const int kend = q0 + BQ;           // causal: only tiles with k0 < kend
    for (int k0 = 0; k0 < kend; k0 += BKV) {
        // load K, V tiles
        for (int idx = tid; idx < BKV * HD; idx += 256) {
            int row = idx >> 6, d = idx & 63;
            k_s[row * PADR + d] = K[(k0 + row) * (NKV * HD) + kvh * HD + d];
            v_s[row * PADR + d] = V[(k0 + row) * (NKV * HD) + kvh * HD + d];
        }
        __syncthreads();

        // scores for this thread's 16 keys: kc = c4*16 + j
        float sv[16];
#pragma unroll
        for (int j = 0; j < 16; j++) sv[j] = 0.f;
        const float* qrow = &q_s[r * PADR];
#pragma unroll 4
        for (int d = 0; d < HD; d += 4) {
            float4 qd = *(const float4*)&qrow[d];
#pragma unroll
            for (int j = 0; j < 16; j++) {
                float4 kv = *(const float4*)&k_s[(c4 * 16 + j) * PADR + d];
                sv[j] += qd.x * kv.x + qd.y * kv.y + qd.z * kv.z + qd.w * kv.w;
            }
        }

        // mask + scale + local max
        float mloc = -INFINITY;
#pragma unroll
        for (int j = 0; j < 16; j++) {
            int kg = k0 + c4 * 16 + j;
            sv[j] = (kg <= qg) ? sv[j] * ATT_SCALE : -1e30f;
            mloc = fmaxf(mloc, sv[j]);
        }
        mloc = fmaxf(mloc, __shfl_xor_sync(0xffffffffu, mloc, 1));
        mloc = fmaxf(mloc, __shfl_xor_sync(0xffffffffu, mloc, 2));

        float mnew  = fmaxf(m, mloc);
        float alpha = __expf(m - mnew);
        float lloc  = 0.f;
#pragma unroll
        for (int j = 0; j < 16; j++) {
            float p = __expf(sv[j] - mnew);
            p_s[r * PADR + c4 * 16 + j] = p;
            lloc += p;
        }
        lloc += __shfl_xor_sync(0xffffffffu, lloc, 1);
        lloc += __shfl_xor_sync(0xffffffffu, lloc, 2);
        l = l * alpha + lloc;
        m = mnew;
#pragma unroll
        for (int j = 0; j < 16; j++) acc[j] *= alpha;

        __syncwarp();   // p_s row produced/consumed within one warp

        // acc[jj] += sum_kc p_s[r][kc] * v_s[kc][c4*16 + jj]
#pragma unroll 4
        for (int kc = 0; kc < BKV; kc++) {
            float p = p_s[r * PADR + kc];
#pragma unroll
            for (int j4 = 0; j4 < 4; j4++) {
                float4 vv = *(const float4*)&v_s[kc * PADR + c4 * 16 + j4 * 4];
                acc[j4 * 4 + 0] += p * vv.x;
                acc[j4 * 4 + 1] += p * vv.y;
                acc[j4 * 4 + 2] += p * vv.z;
                acc[j4 * 4 + 3] += p * vv.w;
            }
        }
        __syncthreads();
    }

    // epilogue: normalize + sink scale
    float lse = m + logf(l);
    float sg  = 1.f / (1.f + __expf(-(lse - sinks[h])));
    float inv = sg / l;
#pragma unroll
    for (int j = 0; j < 16; j++)
        O[qg * (NH * HD) + h * HD + c4 * 16 + j] = acc[j] * inv;
}

// ---------------- launch ----------------------------------------------------
extern "C" void kernel_launch(void* const* d_in, const int* in_sizes, int n_in,
                              void* d_out, int out_size)
{
    const float* x     = (const float*)d_in[0];
    const float* rope  = (const float*)d_in[1];
    const float* wq_w  = (const float*)d_in[2];
    const float* wq_b  = (const float*)d_in[3];
    const float* wk_w  = (const float*)d_in[4];
    const float* wk_b  = (const float*)d_in[5];
    const float* wv_w  = (const float*)d_in[6];
    const float* wv_b  = (const float*)d_in[7];
    const float* wo_w  = (const float*)d_in[8];
    const float* wo_b  = (const float*)d_in[9];
    const float* sinks = (const float*)d_in[10];
    float* out = (float*)d_out;

    float *gq, *gk, *gv, *ga;
    cudaGetSymbolAddress((void**)&gq, g_q);
    cudaGetSymbolAddress((void**)&gk, g_k);
    cudaGetSymbolAddress((void**)&gv, g_v);
    cudaGetSymbolAddress((void**)&ga, g_attn);

    // QKV projections
    sgemm_bias<<<dim3((NH * HD) / BN, S_LEN / BM), 256>>>(x, wq_w, wq_b, gq,
                                                          S_LEN, NH * HD, DIM);
    sgemm_bias<<<dim3((NKV * HD) / BN, S_LEN / BM), 256>>>(x, wk_w, wk_b, gk,
                                                           S_LEN, NKV * HD, DIM);
    sgemm_bias<<<dim3((NKV * HD) / BN, S_LEN / BM), 256>>>(x, wv_w, wv_b, gv,
                                                           S_LEN, NKV * HD, DIM);

    // RoPE on Q and K
    {
        int tq = S_LEN * NH * (HD / 2);
        rope_kernel<<<(tq + 255) / 256, 256>>>(gq, rope, NH);
        int tk = S_LEN * NKV * (HD / 2);
        rope_kernel<<<(tk + 255) / 256, 256>>>(gk, rope, NKV);
    }

    // Flash attention
    {
        int smem = 4 * 64 * PADR * (int)sizeof(float);  // 69632 B
        cudaFuncSetAttribute(attn_kernel,
                             cudaFuncAttributeMaxDynamicSharedMemorySize, smem);
        attn_kernel<<<dim3(S_LEN / BQ, NH), 256, smem>>>(gq, gk, gv, sinks, ga);
    }

    // Output projection
    sgemm_bias<<<dim3(DIM / BN, S_LEN / BM), 256>>>(ga, wo_w, wo_b, out,
                                                    S_LEN, DIM, NH * HD);
}

// round 2
// speedup vs baseline: 1.1521x; 1.1521x over previous
#include <cuda_runtime.h>
#include <math.h>

#define S_LEN 2048
#define DIM   2048
#define NH    32
#define NKV   8
#define HD    64
#define NREP  4           // NH / NKV
#define ATT_SCALE 0.125f  // 1/sqrt(64)

// ---------------- scratch (device globals; no allocation allowed) ----------
__device__ float g_q[S_LEN * NH * HD];     // 16 MB
__device__ float g_k[S_LEN * NKV * HD];    // 4 MB
__device__ float g_v[S_LEN * NKV * HD];    // 4 MB
__device__ float g_attn[S_LEN * NH * HD];  // 16 MB

// ---------------- TF32 tensor-core GEMM ------------------------------------
// C[M,N] = A[M,K] @ B[N,K]^T + bias[N]
// 128x64 block tile, BK=32, 8 warps (2x4), warp tile 64x16, mma.m16n8k8.tf32

__device__ __forceinline__ unsigned f2tf(float f) {
    unsigned r;
    asm("cvt.rna.tf32.f32 %0, %1;" : "=r"(r) : "f"(f));
    return r;
}

__global__ void __launch_bounds__(256)
gemm_tf32(const float* __restrict__ A, const float* __restrict__ B,
          const float* __restrict__ bias, float* __restrict__ C,
          int M, int N, int K)
{
    __shared__ unsigned As[128][36];   // stride 36 words -> conflict-free frags
    __shared__ unsigned Bs[64][36];

    const int tid  = threadIdx.x;
    const int lane = tid & 31;
    const int w    = tid >> 5;
    const int mw   = (w >> 2) * 64;    // warp M offset in tile
    const int nw   = (w & 3) * 16;     // warp N offset in tile
    const int m0   = blockIdx.y * 128;
    const int n0   = blockIdx.x * 64;
    const int g    = lane >> 2;        // group id 0..7
    const int t    = lane & 3;         // thread-in-group 0..3

    float c[4][2][4];
#pragma unroll
    for (int mt = 0; mt < 4; mt++)
#pragma unroll
        for (int nt = 0; nt < 2; nt++)
#pragma unroll
            for (int r = 0; r < 4; r++) c[mt][nt][r] = 0.f;

    for (int k0 = 0; k0 < K; k0 += 32) {
        // fill A tile: 128 rows x 32 cols = 1024 float4 / 256 thr = 4 each
#pragma unroll
        for (int i = 0; i < 4; i++) {
            int lin = tid + i * 256;
            int r   = lin >> 3;
            int c4  = (lin & 7) << 2;
            float4 v = *(const float4*)&A[(m0 + r) * K + k0 + c4];
            As[r][c4 + 0] = f2tf(v.x);
            As[r][c4 + 1] = f2tf(v.y);
            As[r][c4 + 2] = f2tf(v.z);
            As[r][c4 + 3] = f2tf(v.w);
        }
        // fill B tile: 64 rows x 32 cols = 512 float4 / 256 thr = 2 each
#pragma unroll
        for (int i = 0; i < 2; i++) {
            int lin = tid + i * 256;
            int r   = lin >> 3;
            int c4  = (lin & 7) << 2;
            float4 v = *(const float4*)&B[(n0 + r) * K + k0 + c4];
            Bs[r][c4 + 0] = f2tf(v.x);
            Bs[r][c4 + 1] = f2tf(v.y);
            Bs[r][c4 + 2] = f2tf(v.z);
            Bs[r][c4 + 3] = f2tf(v.w);
        }
        __syncthreads();

#pragma unroll
        for (int ks = 0; ks < 4; ks++) {
            const int kk = ks * 8;
            unsigned b[2][2];
#pragma unroll
            for (int nt = 0; nt < 2; nt++) {
                b[nt][0] = Bs[nw + nt * 8 + g][kk + t];
                b[nt][1] = Bs[nw + nt * 8 + g][kk + 4 + t];
            }
#pragma unroll
            for (int mt = 0; mt < 4; mt++) {
                unsigned a0 = As[mw + mt * 16 + g][kk + t];
                unsigned a1 = As[mw + mt * 16 + 8 + g][kk + t];
                unsigned a2 = As[mw + mt * 16 + g][kk + 4 + t];
                unsigned a3 = As[mw + mt * 16 + 8 + g][kk + 4 + t];
#pragma unroll
                for (int nt = 0; nt < 2; nt++) {
                    asm volatile(
                        "mma.sync.aligned.m16n8k8.row.col.f32.tf32.tf32.f32 "
                        "{%0,%1,%2,%3}, {%4,%5,%6,%7}, {%8,%9}, {%0,%1,%2,%3};"
                        : "+f"(c[mt][nt][0]), "+f"(c[mt][nt][1]),
                          "+f"(c[mt][nt][2]), "+f"(c[mt][nt][3])
                        : "r"(a0), "r"(a1), "r"(a2), "r"(a3),
                          "r"(b[nt][0]), "r"(b[nt][1]));
                }
            }
        }
        __syncthreads();
    }

    // epilogue
#pragma unroll
    for (int mt = 0; mt < 4; mt++) {
#pragma unroll
        for (int nt = 0; nt < 2; nt++) {
            int row = m0 + mw + mt * 16 + g;
            int col = n0 + nw + nt * 8 + t * 2;
            float b0 = bias[col], b1 = bias[col + 1];
            C[row * N + col]           = c[mt][nt][0] + b0;
            C[row * N + col + 1]       = c[mt][nt][1] + b1;
            C[(row + 8) * N + col]     = c[mt][nt][2] + b0;
            C[(row + 8) * N + col + 1] = c[mt][nt][3] + b1;
        }
    }
}

// ---------------- RoPE (in place) ------------------------------------------
__global__ void rope_kernel(float* __restrict__ t, const float* __restrict__ rope,
                            int heads)
{
    int idx = blockIdx.x * blockDim.x + threadIdx.x;
    int total = S_LEN * heads * (HD / 2);
    if (idx >= total) return;
    int i = idx % (HD / 2);
    int h = (idx / (HD / 2)) % heads;
    int s = idx / (heads * (HD / 2));
    float c  = rope[s * HD + i];
    float sn = rope[s * HD + HD / 2 + i];
    float* p = t + (s * heads + h) * HD;
    float x1 = p[i], x2 = p[i + HD / 2];
    p[i]           = x1 * c  - x2 * sn;
    p[i + HD / 2]  = x1 * sn + x2 * c;
}

// ---------------- Flash attention with causal mask + sinks -----------------
#define BQ   64
#define BKV  64
#define PADR 68   // row pitch in floats (16B aligned: 68*4=272)

__global__ void __launch_bounds__(256)
attn_kernel(const float* __restrict__ Q, const float* __restrict__ K,
            const float* __restrict__ V, const float* __restrict__ sinks,
            float* __restrict__ O)
{
    extern __shared__ float sm[];
    float* q_s = sm;                    // BQ  * PADR
    float* k_s = q_s + BQ * PADR;       // BKV * PADR
    float* v_s = k_s + BKV * PADR;      // BKV * PADR
    float* p_s = v_s + BKV * PADR;      // BQ  * PADR

    const int h   = blockIdx.y;
    const int q0  = blockIdx.x * BQ;
    const int kvh = h / NREP;
    const int tid = threadIdx.x;
    const int r   = tid >> 2;           // query row within tile (0..63)
    const int c4  = tid & 3;            // 16-wide key/dim slice selector
    const int qg  = q0 + r;

    // load Q tile
    for (int idx = tid; idx < BQ * HD; idx += 256) {
        int row = idx >> 6, d = idx & 63;
        q_s[row * PADR + d] = Q[(q0 + row) * (NH * HD) + h * HD + d];
    }

    float acc[16];
#pragma unroll
    for (int j = 0; j < 16; j++) acc[j] = 0.f;
    float m = -INFINITY, l = 0.f;

    __syncthreads();

    const int kend = q0 + BQ;           // causal: only tiles with k0 < kend
    for (int k0 = 0; k0 < kend; k0 += BKV) {
        // load K, V tiles
        for (int idx = tid; idx < BKV * HD; idx += 256) {
            int row = idx >> 6, d = idx & 63;
            k_s[row * PADR + d] = K[(k0 + row) * (NKV * HD) + kvh * HD + d];
            v_s[row * PADR + d] = V[(k0 + row) * (NKV * HD) + kvh * HD + d];
        }
        __syncthreads();

        // scores for this thread's 16 keys: kc = c4*16 + j
        float sv[16];
#pragma unroll
        for (int j = 0; j < 16; j++) sv[j] = 0.f;
        const float* qrow = &q_s[r * PADR];
#pragma unroll 4
        for (int d = 0; d < HD; d += 4) {
            float4 qd = *(const float4*)&qrow[d];
#pragma unroll
            for (int j = 0; j < 16; j++) {
                float4 kv = *(const float4*)&k_s[(c4 * 16 + j) * PADR + d];
                sv[j] += qd.x * kv.x + qd.y * kv.y + qd.z * kv.z + qd.w * kv.w;
            }
        }

        // mask + scale + local max
        float mloc = -INFINITY;
#pragma unroll
        for (int j = 0; j < 16; j++) {
            int kg = k0 + c4 * 16 + j;
            sv[j] = (kg <= qg) ? sv[j] * ATT_SCALE : -1e30f;
            mloc = fmaxf(mloc, sv[j]);
        }
        mloc = fmaxf(mloc, __shfl_xor_sync(0xffffffffu, mloc, 1));
        mloc = fmaxf(mloc, __shfl_xor_sync(0xffffffffu, mloc, 2));

        float mnew  = fmaxf(m, mloc);
        float alpha = __expf(m - mnew);
        float lloc  = 0.f;
#pragma unroll
        for (int j = 0; j < 16; j++) {
            float p = __expf(sv[j] - mnew);
            p_s[r * PADR + c4 * 16 + j] = p;
            lloc += p;
        }
        lloc += __shfl_xor_sync(0xffffffffu, lloc, 1);
        lloc += __shfl_xor_sync(0xffffffffu, lloc, 2);
        l = l * alpha + lloc;
        m = mnew;
#pragma unroll
        for (int j = 0; j < 16; j++) acc[j] *= alpha;

        __syncwarp();   // p_s row produced/consumed within one warp

        // acc[jj] += sum_kc p_s[r][kc] * v_s[kc][c4*16 + jj]
#pragma unroll 4
        for (int kc = 0; kc < BKV; kc++) {
            float p = p_s[r * PADR + kc];
#pragma unroll
            for (int j4 = 0; j4 < 4; j4++) {
                float4 vv = *(const float4*)&v_s[kc * PADR + c4 * 16 + j4 * 4];
                acc[j4 * 4 + 0] += p * vv.x;
                acc[j4 * 4 + 1] += p * vv.y;
                acc[j4 * 4 + 2] += p * vv.z;
                acc[j4 * 4 + 3] += p * vv.w;
            }
        }
        __syncthreads();
    }

    // epilogue: normalize + sink scale
    float lse = m + logf(l);
    float sg  = 1.f / (1.f + __expf(-(lse - sinks[h])));
    float inv = sg / l;
#pragma unroll
    for (int j = 0; j < 16; j++)
        O[qg * (NH * HD) + h * HD + c4 * 16 + j] = acc[j] * inv;
}

// ---------------- launch ----------------------------------------------------
extern "C" void kernel_launch(void* const* d_in, const int* in_sizes, int n_in,
                              void* d_out, int out_size)
{
    const float* x     = (const float*)d_in[0];
    const float* rope  = (const float*)d_in[1];
    const float* wq_w  = (const float*)d_in[2];
    const float* wq_b  = (const float*)d_in[3];
    const float* wk_w  = (const float*)d_in[4];
    const float* wk_b  = (const float*)d_in[5];
    const float* wv_w  = (const float*)d_in[6];
    const float* wv_b  = (const float*)d_in[7];
    const float* wo_w  = (const float*)d_in[8];
    const float* wo_b  = (const float*)d_in[9];
    const float* sinks = (const float*)d_in[10];
    float* out = (float*)d_out;

    float *gq, *gk, *gv, *ga;
    cudaGetSymbolAddress((void**)&gq, g_q);
    cudaGetSymbolAddress((void**)&gk, g_k);
    cudaGetSymbolAddress((void**)&gv, g_v);
    cudaGetSymbolAddress((void**)&ga, g_attn);

    // QKV projections (tf32 tensor cores)
    gemm_tf32<<<dim3((NH * HD) / 64, S_LEN / 128), 256>>>(x, wq_w, wq_b, gq,
                                                          S_LEN, NH * HD, DIM);
    gemm_tf32<<<dim3((NKV * HD) / 64, S_LEN / 128), 256>>>(x, wk_w, wk_b, gk,
                                                           S_LEN, NKV * HD, DIM);
    gemm_tf32<<<dim3((NKV * HD) / 64, S_LEN / 128), 256>>>(x, wv_w, wv_b, gv,
                                                           S_LEN, NKV * HD, DIM);

    // RoPE on Q and K
    {
        int tq = S_LEN * NH * (HD / 2);
        rope_kernel<<<(tq + 255) / 256, 256>>>(gq, rope, NH);
        int tk = S_LEN * NKV * (HD / 2);
        rope_kernel<<<(tk + 255) / 256, 256>>>(gk, rope, NKV);
    }

    // Flash attention
    {
        int smem = 4 * 64 * PADR * (int)sizeof(float);  // 69632 B
        cudaFuncSetAttribute(attn_kernel,
                             cudaFuncAttributeMaxDynamicSharedMemorySize, smem);
        attn_kernel<<<dim3(S_LEN / BQ, NH), 256, smem>>>(gq, gk, gv, sinks, ga);
    }

    // Output projection (tf32 tensor cores)
    gemm_tf32<<<dim3(DIM / 64, S_LEN / 128), 256>>>(ga, wo_w, wo_b, out,
                                                    S_LEN, DIM, NH * HD);
}

// round 3
// speedup vs baseline: 6.0598x; 5.2598x over previous
#include <cuda_runtime.h>
#include <math.h>

#define S_LEN 2048
#define DIM   2048
#define NH    32
#define NKV   8
#define HD    64
#define NREP  4           // NH / NKV
#define ATT_SCALE 0.125f  // 1/sqrt(64)

// ---------------- scratch (device globals; no allocation allowed) ----------
__device__ float g_q[S_LEN * NH * HD];     // 16 MB
__device__ float g_k[S_LEN * NKV * HD];    // 4 MB
__device__ float g_v[S_LEN * NKV * HD];    // 4 MB
__device__ float g_attn[S_LEN * NH * HD];  // 16 MB

__device__ __forceinline__ unsigned f2tf(float f) {
    unsigned r;
    asm("cvt.rna.tf32.f32 %0, %1;" : "=r"(r) : "f"(f));
    return r;
}

// ---------------- TF32 tensor-core GEMM ------------------------------------
// C[M,N] = A[M,K] @ B[N,K]^T + bias[N]
// 128x64 block tile, BK=32, 8 warps (2x4), warp tile 64x16, mma.m16n8k8.tf32
__global__ void __launch_bounds__(256)
gemm_tf32(const float* __restrict__ A, const float* __restrict__ B,
          const float* __restrict__ bias, float* __restrict__ C,
          int M, int N, int K)
{
    __shared__ unsigned As[128][36];
    __shared__ unsigned Bs[64][36];

    const int tid  = threadIdx.x;
    const int lane = tid & 31;
    const int w    = tid >> 5;
    const int mw   = (w >> 2) * 64;
    const int nw   = (w & 3) * 16;
    const int m0   = blockIdx.y * 128;
    const int n0   = blockIdx.x * 64;
    const int g    = lane >> 2;
    const int t    = lane & 3;

    float c[4][2][4];
#pragma unroll
    for (int mt = 0; mt < 4; mt++)
#pragma unroll
        for (int nt = 0; nt < 2; nt++)
#pragma unroll
            for (int r = 0; r < 4; r++) c[mt][nt][r] = 0.f;

    for (int k0 = 0; k0 < K; k0 += 32) {
#pragma unroll
        for (int i = 0; i < 4; i++) {
            int lin = tid + i * 256;
            int r   = lin >> 3;
            int c4  = (lin & 7) << 2;
            float4 v = *(const float4*)&A[(m0 + r) * K + k0 + c4];
            As[r][c4 + 0] = f2tf(v.x);
            As[r][c4 + 1] = f2tf(v.y);
            As[r][c4 + 2] = f2tf(v.z);
            As[r][c4 + 3] = f2tf(v.w);
        }
#pragma unroll
        for (int i = 0; i < 2; i++) {
            int lin = tid + i * 256;
            int r   = lin >> 3;
            int c4  = (lin & 7) << 2;
            float4 v = *(const float4*)&B[(n0 + r) * K + k0 + c4];
            Bs[r][c4 + 0] = f2tf(v.x);
            Bs[r][c4 + 1] = f2tf(v.y);
            Bs[r][c4 + 2] = f2tf(v.z);
            Bs[r][c4 + 3] = f2tf(v.w);
        }
        __syncthreads();

#pragma unroll
        for (int ks = 0; ks < 4; ks++) {
            const int kk = ks * 8;
            unsigned b[2][2];
#pragma unroll
            for (int nt = 0; nt < 2; nt++) {
                b[nt][0] = Bs[nw + nt * 8 + g][kk + t];
                b[nt][1] = Bs[nw + nt * 8 + g][kk + 4 + t];
            }
#pragma unroll
            for (int mt = 0; mt < 4; mt++) {
                unsigned a0 = As[mw + mt * 16 + g][kk + t];
                unsigned a1 = As[mw + mt * 16 + 8 + g][kk + t];
                unsigned a2 = As[mw + mt * 16 + g][kk + 4 + t];
                unsigned a3 = As[mw + mt * 16 + 8 + g][kk + 4 + t];
#pragma unroll
                for (int nt = 0; nt < 2; nt++) {
                    asm volatile(
                        "mma.sync.aligned.m16n8k8.row.col.f32.tf32.tf32.f32 "
                        "{%0,%1,%2,%3}, {%4,%5,%6,%7}, {%8,%9}, {%0,%1,%2,%3};"
                        : "+f"(c[mt][nt][0]), "+f"(c[mt][nt][1]),
                          "+f"(c[mt][nt][2]), "+f"(c[mt][nt][3])
                        : "r"(a0), "r"(a1), "r"(a2), "r"(a3),
                          "r"(b[nt][0]), "r"(b[nt][1]));
                }
            }
        }
        __syncthreads();
    }

#pragma unroll
    for (int mt = 0; mt < 4; mt++) {
#pragma unroll
        for (int nt = 0; nt < 2; nt++) {
            int row = m0 + mw + mt * 16 + g;
            int col = n0 + nw + nt * 8 + t * 2;
            float b0 = bias[col], b1 = bias[col + 1];
            C[row * N + col]           = c[mt][nt][0] + b0;
            C[row * N + col + 1]       = c[mt][nt][1] + b1;
            C[(row + 8) * N + col]     = c[mt][nt][2] + b0;
            C[(row + 8) * N + col + 1] = c[mt][nt][3] + b1;
        }
    }
}

// ---------------- RoPE (in place) ------------------------------------------
__global__ void rope_kernel(float* __restrict__ t, const float* __restrict__ rope,
                            int heads)
{
    int idx = blockIdx.x * blockDim.x + threadIdx.x;
    int total = S_LEN * heads * (HD / 2);
    if (idx >= total) return;
    int i = idx % (HD / 2);
    int h = (idx / (HD / 2)) % heads;
    int s = idx / (heads * (HD / 2));
    float c  = rope[s * HD + i];
    float sn = rope[s * HD + HD / 2 + i];
    float* p = t + (s * heads + h) * HD;
    float x1 = p[i], x2 = p[i + HD / 2];
    p[i]           = x1 * c  - x2 * sn;
    p[i + HD / 2]  = x1 * sn + x2 * c;
}

// ---------------- Tensor-core flash attention (tf32 mma) --------------------
// 64x64 tiles. 4 warps, each owns 16 query rows. Stride-68 smem rows make all
// mma fragment LDS accesses conflict-free (bank = (4g+t) mod 32, a permutation).
#define ASTR 68

__global__ void __launch_bounds__(128)
attn_mma(const float* __restrict__ Q, const float* __restrict__ K,
         const float* __restrict__ V, const float* __restrict__ sinks,
         float* __restrict__ O)
{
    extern __shared__ unsigned sm_u[];
    unsigned* q_s = sm_u;                  // [64][ASTR] tf32
    unsigned* k_s = q_s + 64 * ASTR;       // [64][ASTR] tf32
    unsigned* v_s = k_s + 64 * ASTR;       // [64][ASTR] tf32, TRANSPOSED: [dim][key]
    unsigned* p_s = v_s + 64 * ASTR;       // [64][ASTR] tf32

    const int h    = blockIdx.y;
    const int q0   = blockIdx.x * 64;
    const int kvh  = h >> 2;               // h / NREP
    const int tid  = threadIdx.x;
    const int lane = tid & 31;
    const int w    = tid >> 5;
    const int g    = lane >> 2;
    const int t    = lane & 3;
    const int mw   = w * 16;               // warp's query-row offset in tile

    // ---- load Q tile (64 rows x 64 dims) ----
#pragma unroll
    for (int i = 0; i < 8; i++) {
        int idx = tid + i * 128;
        int row = idx >> 4, c4 = (idx & 15) << 2;
        float4 v4 = *(const float4*)&Q[(q0 + row) * (NH * HD) + h * HD + c4];
        q_s[row * ASTR + c4 + 0] = f2tf(v4.x);
        q_s[row * ASTR + c4 + 1] = f2tf(v4.y);
        q_s[row * ASTR + c4 + 2] = f2tf(v4.z);
        q_s[row * ASTR + c4 + 3] = f2tf(v4.w);
    }

    float o[8][4];
#pragma unroll
    for (int nt = 0; nt < 8; nt++)
#pragma unroll
        for (int r = 0; r < 4; r++) o[nt][r] = 0.f;
    float m_a = -INFINITY, l_a = 0.f, m_b = -INFINITY, l_b = 0.f;

    __syncthreads();

    const int qg_a = q0 + mw + g;
    const int qg_b = qg_a + 8;

    for (int k0 = 0; k0 < q0 + 64; k0 += 64) {
        // ---- load K (natural) and V (transposed) ----
#pragma unroll
        for (int i = 0; i < 8; i++) {
            int idx = tid + i * 128;
            int row = idx >> 4, c4 = (idx & 15) << 2;
            const float* kp = &K[(k0 + row) * (NKV * HD) + kvh * HD + c4];
            float4 k4 = *(const float4*)kp;
            k_s[row * ASTR + c4 + 0] = f2tf(k4.x);
            k_s[row * ASTR + c4 + 1] = f2tf(k4.y);
            k_s[row * ASTR + c4 + 2] = f2tf(k4.z);
            k_s[row * ASTR + c4 + 3] = f2tf(k4.w);
            const float* vp = &V[(k0 + row) * (NKV * HD) + kvh * HD + c4];
            float4 v4 = *(const float4*)vp;
            v_s[(c4 + 0) * ASTR + row] = f2tf(v4.x);
            v_s[(c4 + 1) * ASTR + row] = f2tf(v4.y);
            v_s[(c4 + 2) * ASTR + row] = f2tf(v4.z);
            v_s[(c4 + 3) * ASTR + row] = f2tf(v4.w);
        }
        __syncthreads();

        // ---- S = Q @ K^T (this warp's 16 rows x 64 keys) ----
        float s[8][4];
#pragma unroll
        for (int nt = 0; nt < 8; nt++)
#pragma unroll
            for (int r = 0; r < 4; r++) s[nt][r] = 0.f;

#pragma unroll
        for (int ks = 0; ks < 8; ks++) {
            const int kk = ks * 8;
            unsigned a0 = q_s[(mw + g) * ASTR + kk + t];
            unsigned a1 = q_s[(mw + 8 + g) * ASTR + kk + t];
            unsigned a2 = q_s[(mw + g) * ASTR + kk + 4 + t];
            unsigned a3 = q_s[(mw + 8 + g) * ASTR + kk + 4 + t];
#pragma unroll
            for (int nt = 0; nt < 8; nt++) {
                unsigned b0 = k_s[(nt * 8 + g) * ASTR + kk + t];
                unsigned b1 = k_s[(nt * 8 + g) * ASTR + kk + 4 + t];
                asm volatile(
                    "mma.sync.aligned.m16n8k8.row.col.f32.tf32.tf32.f32 "
                    "{%0,%1,%2,%3}, {%4,%5,%6,%7}, {%8,%9}, {%0,%1,%2,%3};"
                    : "+f"(s[nt][0]), "+f"(s[nt][1]), "+f"(s[nt][2]), "+f"(s[nt][3])
                    : "r"(a0), "r"(a1), "r"(a2), "r"(a3), "r"(b0), "r"(b1));
            }
        }

        // ---- scale + causal mask (mask only on the diagonal tile) ----
        if (k0 == q0) {
#pragma unroll
            for (int nt = 0; nt < 8; nt++) {
                int kg0 = k0 + nt * 8 + 2 * t;
                s[nt][0] = (kg0     <= qg_a) ? s[nt][0] * ATT_SCALE : -1e30f;
                s[nt][1] = (kg0 + 1 <= qg_a) ? s[nt][1] * ATT_SCALE : -1e30f;
                s[nt][2] = (kg0     <= qg_b) ? s[nt][2] * ATT_SCALE : -1e30f;
                s[nt][3] = (kg0 + 1 <= qg_b) ? s[nt][3] * ATT_SCALE : -1e30f;
            }
        } else {
#pragma unroll
            for (int nt = 0; nt < 8; nt++)
#pragma unroll
                for (int r = 0; r < 4; r++) s[nt][r] *= ATT_SCALE;
        }

        // ---- online softmax (rows g and g+8) ----
        float mlA = -INFINITY, mlB = -INFINITY;
#pragma unroll
        for (int nt = 0; nt < 8; nt++) {
            mlA = fmaxf(mlA, fmaxf(s[nt][0], s[nt][1]));
            mlB = fmaxf(mlB, fmaxf(s[nt][2], s[nt][3]));
        }
        mlA = fmaxf(mlA, __shfl_xor_sync(0xffffffffu, mlA, 1));
        mlA = fmaxf(mlA, __shfl_xor_sync(0xffffffffu, mlA, 2));
        mlB = fmaxf(mlB, __shfl_xor_sync(0xffffffffu, mlB, 1));
        mlB = fmaxf(mlB, __shfl_xor_sync(0xffffffffu, mlB, 2));

        float mnA = fmaxf(m_a, mlA), mnB = fmaxf(m_b, mlB);
        float alA = __expf(m_a - mnA), alB = __expf(m_b - mnB);

        float sumA = 0.f, sumB = 0.f;
#pragma unroll
        for (int nt = 0; nt < 8; nt++) {
            float p0 = __expf(s[nt][0] - mnA);
            float p1 = __expf(s[nt][1] - mnA);
            float p2 = __expf(s[nt][2] - mnB);
            float p3 = __expf(s[nt][3] - mnB);
            sumA += p0 + p1;
            sumB += p2 + p3;
            int col = nt * 8 + 2 * t;
            p_s[(mw + g) * ASTR + col]     = f2tf(p0);
            p_s[(mw + g) * ASTR + col + 1] = f2tf(p1);
            p_s[(mw + 8 + g) * ASTR + col]     = f2tf(p2);
            p_s[(mw + 8 + g) * ASTR + col + 1] = f2tf(p3);
        }
        sumA += __shfl_xor_sync(0xffffffffu, sumA, 1);
        sumA += __shfl_xor_sync(0xffffffffu, sumA, 2);
        sumB += __shfl_xor_sync(0xffffffffu, sumB, 1);
        sumB += __shfl_xor_sync(0xffffffffu, sumB, 2);

        l_a = l_a * alA + sumA;  m_a = mnA;
        l_b = l_b * alB + sumB;  m_b = mnB;

#pragma unroll
        for (int nt = 0; nt < 8; nt++) {
            o[nt][0] *= alA; o[nt][1] *= alA;
            o[nt][2] *= alB; o[nt][3] *= alB;
        }

        __syncwarp();   // p_s rows are produced and consumed by this warp only

        // ---- O += P @ V  (A = p_s rows, B = v_s transposed tile) ----
#pragma unroll
        for (int ks = 0; ks < 8; ks++) {
            const int kk = ks * 8;
            unsigned a0 = p_s[(mw + g) * ASTR + kk + t];
            unsigned a1 = p_s[(mw + 8 + g) * ASTR + kk + t];
            unsigned a2 = p_s[(mw + g) * ASTR + kk + 4 + t];
            unsigned a3 = p_s[(mw + 8 + g) * ASTR + kk + 4 + t];
#pragma unroll
            for (int nt = 0; nt < 8; nt++) {
                unsigned b0 = v_s[(nt * 8 + g) * ASTR + kk + t];
                unsigned b1 = v_s[(nt * 8 + g) * ASTR + kk + 4 + t];
                asm volatile(
                    "mma.sync.aligned.m16n8k8.row.col.f32.tf32.tf32.f32 "
                    "{%0,%1,%2,%3}, {%4,%5,%6,%7}, {%8,%9}, {%0,%1,%2,%3};"
                    : "+f"(o[nt][0]), "+f"(o[nt][1]), "+f"(o[nt][2]), "+f"(o[nt][3])
                    : "r"(a0), "r"(a1), "r"(a2), "r"(a3), "r"(b0), "r"(b1));
            }
        }
        __syncthreads();   // all warps done with k_s/v_s before next load
    }

    // ---- epilogue: normalize + sink scale ----
    float lseA = m_a + logf(l_a);
    float lseB = m_b + logf(l_b);
    float snk  = sinks[h];
    float invA = (1.f / (1.f + __expf(-(lseA - snk)))) / l_a;
    float invB = (1.f / (1.f + __expf(-(lseB - snk)))) / l_b;

#pragma unroll
    for (int nt = 0; nt < 8; nt++) {
        int col = nt * 8 + 2 * t;
        float* oa = &O[qg_a * (NH * HD) + h * HD + col];
        float* ob = &O[qg_b * (NH * HD) + h * HD + col];
        oa[0] = o[nt][0] * invA;
        oa[1] = o[nt][1] * invA;
        ob[0] = o[nt][2] * invB;
        ob[1] = o[nt][3] * invB;
    }
}

// ---------------- launch ----------------------------------------------------
extern "C" void kernel_launch(void* const* d_in, const int* in_sizes, int n_in,
                              void* d_out, int out_size)
{
    const float* x     = (const float*)d_in[0];
    const float* rope  = (const float*)d_in[1];
    const float* wq_w  = (const float*)d_in[2];
    const float* wq_b  = (const float*)d_in[3];
    const float* wk_w  = (const float*)d_in[4];
    const float* wk_b  = (const float*)d_in[5];
    const float* wv_w  = (const float*)d_in[6];
    const float* wv_b  = (const float*)d_in[7];
    const float* wo_w  = (const float*)d_in[8];
    const float* wo_b  = (const float*)d_in[9];
    const float* sinks = (const float*)d_in[10];
    float* out = (float*)d_out;

    float *gq, *gk, *gv, *ga;
    cudaGetSymbolAddress((void**)&gq, g_q);
    cudaGetSymbolAddress((void**)&gk, g_k);
    cudaGetSymbolAddress((void**)&gv, g_v);
    cudaGetSymbolAddress((void**)&ga, g_attn);

    // QKV projections (tf32 tensor cores)
    gemm_tf32<<<dim3((NH * HD) / 64, S_LEN / 128), 256>>>(x, wq_w, wq_b, gq,
                                                          S_LEN, NH * HD, DIM);
    gemm_tf32<<<dim3((NKV * HD) / 64, S_LEN / 128), 256>>>(x, wk_w, wk_b, gk,
                                                           S_LEN, NKV * HD, DIM);
    gemm_tf32<<<dim3((NKV * HD) / 64, S_LEN / 128), 256>>>(x, wv_w, wv_b, gv,
                                                           S_LEN, NKV * HD, DIM);

    // RoPE on Q and K
    {
        int tq = S_LEN * NH * (HD / 2);
        rope_kernel<<<(tq + 255) / 256, 256>>>(gq, rope, NH);
        int tk = S_LEN * NKV * (HD / 2);
        rope_kernel<<<(tk + 255) / 256, 256>>>(gk, rope, NKV);
    }

    // Flash attention (tf32 tensor cores)
    {
        int smem = 4 * 64 * ASTR * (int)sizeof(unsigned);  // 69632 B
        cudaFuncSetAttribute(attn_mma,
                             cudaFuncAttributeMaxDynamicSharedMemorySize, smem);
        attn_mma<<<dim3(S_LEN / 64, NH), 128, smem>>>(gq, gk, gv, sinks, ga);
    }

    // Output projection (tf32 tensor cores)
    gemm_tf32<<<dim3(DIM / 64, S_LEN / 128), 256>>>(ga, wo_w, wo_b, out,
                                                    S_LEN, DIM, NH * HD);
}

// round 4
// speedup vs baseline: 7.8022x; 1.2875x over previous
#include <cuda_runtime.h>
#include <math.h>

#define S_LEN 2048
#define DIM   2048
#define NH    32
#define NKV   8
#define HD    64
#define NREP  4           // NH / NKV
#define ATT_SCALE 0.125f  // 1/sqrt(64)

// ---------------- scratch (device globals; no allocation allowed) ----------
__device__ float g_q[S_LEN * NH * HD];     // 16 MB
__device__ float g_k[S_LEN * NKV * HD];    // 4 MB
__device__ float g_v[S_LEN * NKV * HD];    // 4 MB
__device__ float g_attn[S_LEN * NH * HD];  // 16 MB

__device__ __forceinline__ unsigned f2tf(float f) {
    unsigned r;
    asm("cvt.rna.tf32.f32 %0, %1;" : "=r"(r) : "f"(f));
    return r;
}

__device__ __forceinline__ void cpasync16(void* smem_ptr, const void* gptr) {
    unsigned s = (unsigned)__cvta_generic_to_shared(smem_ptr);
    asm volatile("cp.async.cg.shared.global [%0], [%1], 16;\n" :: "r"(s), "l"(gptr));
}
__device__ __forceinline__ void cp_commit() {
    asm volatile("cp.async.commit_group;\n");
}
__device__ __forceinline__ void cp_wait0() {
    asm volatile("cp.async.wait_group 0;\n");
}

// ---------------- TF32 tensor-core GEMM core --------------------------------
// C[M,N] = A[M,K] @ B[N,K]^T + bias[N]
// 128x128 block tile, BK=32, double-buffered cp.async, 8 warps (2x4),
// warp tile 64x32, mma.m16n8k8.tf32. smem rows stride 36 -> all fragment
// LDS are conflict-free (bank = 4g+t, a permutation of 0..31).
#define GSTR  36
#define TILEW (128 * GSTR)   // words per (A or B) tile buffer

__device__ __forceinline__ void gemm_core(
    const float* __restrict__ A, const float* __restrict__ B,
    const float* __restrict__ bias, float* __restrict__ C,
    int N, int K, int m0, int n0, float* sm)
{
    float* As = sm;                 // [2][128][GSTR]
    float* Bs = sm + 2 * TILEW;     // [2][128][GSTR]

    const int tid  = threadIdx.x;
    const int lane = tid & 31;
    const int w    = tid >> 5;
    const int mw   = (w >> 2) * 64;
    const int nw   = (w & 3) * 32;
    const int g    = lane >> 2;
    const int t    = lane & 3;

    const int lr = tid >> 3;          // 0..31 rows per 256-thread pass
    const int lc = (tid & 7) << 2;    // 0,4,..28

    float acc[4][4][4];
#pragma unroll
    for (int mt = 0; mt < 4; mt++)
#pragma unroll
        for (int nt = 0; nt < 4; nt++)
#pragma unroll
            for (int r = 0; r < 4; r++) acc[mt][nt][r] = 0.f;

    const int ntiles = K >> 5;

    // ---- prologue: stage 0 ----
#pragma unroll
    for (int i = 0; i < 4; i++) {
        int r = lr + i * 32;
        cpasync16(&As[r * GSTR + lc], &A[(m0 + r) * K + lc]);
        cpasync16(&Bs[r * GSTR + lc], &B[(n0 + r) * K + lc]);
    }
    cp_commit();
    cp_wait0();
    __syncthreads();

    int st = 0;
    for (int kt = 0; kt < ntiles; kt++) {
        // issue next-stage loads (overlap with compute)
        if (kt + 1 < ntiles) {
            const int k0 = (kt + 1) << 5;
            float* an = As + (st ^ 1) * TILEW;
            float* bn = Bs + (st ^ 1) * TILEW;
#pragma unroll
            for (int i = 0; i < 4; i++) {
                int r = lr + i * 32;
                cpasync16(&an[r * GSTR + lc], &A[(m0 + r) * K + k0 + lc]);
                cpasync16(&bn[r * GSTR + lc], &B[(n0 + r) * K + k0 + lc]);
            }
            cp_commit();
        }

        const float* ac = As + st * TILEW;
        const float* bc = Bs + st * TILEW;
#pragma unroll
        for (int ks = 0; ks < 4; ks++) {
            const int kk = ks * 8;
            unsigned bf[4][2];
#pragma unroll
            for (int nt = 0; nt < 4; nt++) {
                bf[nt][0] = f2tf(bc[(nw + nt * 8 + g) * GSTR + kk + t]);
                bf[nt][1] = f2tf(bc[(nw + nt * 8 + g) * GSTR + kk + 4 + t]);
            }
#pragma unroll
            for (int mt = 0; mt < 4; mt++) {
                unsigned a0 = f2tf(ac[(mw + mt * 16 + g) * GSTR + kk + t]);
                unsigned a1 = f2tf(ac[(mw + mt * 16 + 8 + g) * GSTR + kk + t]);
                unsigned a2 = f2tf(ac[(mw + mt * 16 + g) * GSTR + kk + 4 + t]);
                unsigned a3 = f2tf(ac[(mw + mt * 16 + 8 + g) * GSTR + kk + 4 + t]);
#pragma unroll
                for (int nt = 0; nt < 4; nt++) {
                    asm volatile(
                        "mma.sync.aligned.m16n8k8.row.col.f32.tf32.tf32.f32 "
                        "{%0,%1,%2,%3}, {%4,%5,%6,%7}, {%8,%9}, {%0,%1,%2,%3};"
                        : "+f"(acc[mt][nt][0]), "+f"(acc[mt][nt][1]),
                          "+f"(acc[mt][nt][2]), "+f"(acc[mt][nt][3])
                        : "r"(a0), "r"(a1), "r"(a2), "r"(a3),
                          "r"(bf[nt][0]), "r"(bf[nt][1]));
                }
            }
        }

        if (kt + 1 < ntiles) cp_wait0();
        __syncthreads();
        st ^= 1;
    }

    // ---- epilogue ----
#pragma unroll
    for (int mt = 0; mt < 4; mt++) {
#pragma unroll
        for (int nt = 0; nt < 4; nt++) {
            int row = m0 + mw + mt * 16 + g;
            int col = n0 + nw + nt * 8 + t * 2;
            float b0 = bias[col], b1 = bias[col + 1];
            C[row * N + col]           = acc[mt][nt][0] + b0;
            C[row * N + col + 1]       = acc[mt][nt][1] + b1;
            C[(row + 8) * N + col]     = acc[mt][nt][2] + b0;
            C[(row + 8) * N + col + 1] = acc[mt][nt][3] + b1;
        }
    }
}

#define GEMM_SMEM (4 * TILEW * (int)sizeof(float))   // 73728 B

// Fused QKV projection: block column selects which weight/output.
__global__ void __launch_bounds__(256)
qkv_gemm(const float* __restrict__ x,
         const float* __restrict__ wq, const float* __restrict__ bq, float* __restrict__ oq,
         const float* __restrict__ wk, const float* __restrict__ bk, float* __restrict__ ok,
         const float* __restrict__ wv, const float* __restrict__ bv, float* __restrict__ ov)
{
    extern __shared__ float sm[];
    const int bx = blockIdx.x;
    const float *B, *bias; float* C; int N, n0;
    if (bx < 16)      { B = wq; bias = bq; C = oq; N = 2048; n0 = bx * 128; }
    else if (bx < 20) { B = wk; bias = bk; C = ok; N = 512;  n0 = (bx - 16) * 128; }
    else              { B = wv; bias = bv; C = ov; N = 512;  n0 = (bx - 20) * 128; }
    gemm_core(x, B, bias, C, N, DIM, blockIdx.y * 128, n0, sm);
}

// Generic GEMM (output projection)
__global__ void __launch_bounds__(256)
gemm2(const float* __restrict__ A, const float* __restrict__ B,
      const float* __restrict__ bias, float* __restrict__ C, int N, int K)
{
    extern __shared__ float sm[];
    gemm_core(A, B, bias, C, N, K, blockIdx.y * 128, blockIdx.x * 128, sm);
}

// ---------------- RoPE (in place) ------------------------------------------
__global__ void rope_kernel(float* __restrict__ t, const float* __restrict__ rope,
                            int heads)
{
    int idx = blockIdx.x * blockDim.x + threadIdx.x;
    int total = S_LEN * heads * (HD / 2);
    if (idx >= total) return;
    int i = idx % (HD / 2);
    int h = (idx / (HD / 2)) % heads;
    int s = idx / (heads * (HD / 2));
    float c  = rope[s * HD + i];
    float sn = rope[s * HD + HD / 2 + i];
    float* p = t + (s * heads + h) * HD;
    float x1 = p[i], x2 = p[i + HD / 2];
    p[i]           = x1 * c  - x2 * sn;
    p[i + HD / 2]  = x1 * sn + x2 * c;
}

// ---------------- Tensor-core flash attention (tf32 mma) --------------------
#define ASTR 68

__global__ void __launch_bounds__(128)
attn_mma(const float* __restrict__ Q, const float* __restrict__ K,
         const float* __restrict__ V, const float* __restrict__ sinks,
         float* __restrict__ O)
{
    extern __shared__ unsigned sm_u[];
    unsigned* q_s = sm_u;                  // [64][ASTR] tf32
    unsigned* k_s = q_s + 64 * ASTR;       // [64][ASTR] tf32
    unsigned* v_s = k_s + 64 * ASTR;       // [64][ASTR] tf32, TRANSPOSED: [dim][key]
    unsigned* p_s = v_s + 64 * ASTR;       // [64][ASTR] tf32

    const int h    = blockIdx.y;
    const int q0   = blockIdx.x * 64;
    const int kvh  = h >> 2;               // h / NREP
    const int tid  = threadIdx.x;
    const int lane = tid & 31;
    const int w    = tid >> 5;
    const int g    = lane >> 2;
    const int t    = lane & 3;
    const int mw   = w * 16;

    // ---- load Q tile ----
#pragma unroll
    for (int i = 0; i < 8; i++) {
        int idx = tid + i * 128;
        int row = idx >> 4, c4 = (idx & 15) << 2;
        float4 v4 = *(const float4*)&Q[(q0 + row) * (NH * HD) + h * HD + c4];
        q_s[row * ASTR + c4 + 0] = f2tf(v4.x);
        q_s[row * ASTR + c4 + 1] = f2tf(v4.y);
        q_s[row * ASTR + c4 + 2] = f2tf(v4.z);
        q_s[row * ASTR + c4 + 3] = f2tf(v4.w);
    }

    float o[8][4];
#pragma unroll
    for (int nt = 0; nt < 8; nt++)
#pragma unroll
        for (int r = 0; r < 4; r++) o[nt][r] = 0.f;
    float m_a = -INFINITY, l_a = 0.f, m_b = -INFINITY, l_b = 0.f;

    __syncthreads();

    const int qg_a = q0 + mw + g;
    const int qg_b = qg_a + 8;

    for (int k0 = 0; k0 < q0 + 64; k0 += 64) {
#pragma unroll
        for (int i = 0; i < 8; i++) {
            int idx = tid + i * 128;
            int row = idx >> 4, c4 = (idx & 15) << 2;
            float4 k4 = *(const float4*)&K[(k0 + row) * (NKV * HD) + kvh * HD + c4];
            k_s[row * ASTR + c4 + 0] = f2tf(k4.x);
            k_s[row * ASTR + c4 + 1] = f2tf(k4.y);
            k_s[row * ASTR + c4 + 2] = f2tf(k4.z);
            k_s[row * ASTR + c4 + 3] = f2tf(k4.w);
            float4 v4 = *(const float4*)&V[(k0 + row) * (NKV * HD) + kvh * HD + c4];
            v_s[(c4 + 0) * ASTR + row] = f2tf(v4.x);
            v_s[(c4 + 1) * ASTR + row] = f2tf(v4.y);
            v_s[(c4 + 2) * ASTR + row] = f2tf(v4.z);
            v_s[(c4 + 3) * ASTR + row] = f2tf(v4.w);
        }
        __syncthreads();

        float s[8][4];
#pragma unroll
        for (int nt = 0; nt < 8; nt++)
#pragma unroll
            for (int r = 0; r < 4; r++) s[nt][r] = 0.f;

#pragma unroll
        for (int ks = 0; ks < 8; ks++) {
            const int kk = ks * 8;
            unsigned a0 = q_s[(mw + g) * ASTR + kk + t];
            unsigned a1 = q_s[(mw + 8 + g) * ASTR + kk + t];
            unsigned a2 = q_s[(mw + g) * ASTR + kk + 4 + t];
            unsigned a3 = q_s[(mw + 8 + g) * ASTR + kk + 4 + t];
#pragma unroll
            for (int nt = 0; nt < 8; nt++) {
                unsigned b0 = k_s[(nt * 8 + g) * ASTR + kk + t];
                unsigned b1 = k_s[(nt * 8 + g) * ASTR + kk + 4 + t];
                asm volatile(
                    "mma.sync.aligned.m16n8k8.row.col.f32.tf32.tf32.f32 "
                    "{%0,%1,%2,%3}, {%4,%5,%6,%7}, {%8,%9}, {%0,%1,%2,%3};"
                    : "+f"(s[nt][0]), "+f"(s[nt][1]), "+f"(s[nt][2]), "+f"(s[nt][3])
                    : "r"(a0), "r"(a1), "r"(a2), "r"(a3), "r"(b0), "r"(b1));
            }
        }

        if (k0 == q0) {
#pragma unroll
            for (int nt = 0; nt < 8; nt++) {
                int kg0 = k0 + nt * 8 + 2 * t;
                s[nt][0] = (kg0     <= qg_a) ? s[nt][0] * ATT_SCALE : -1e30f;
                s[nt][1] = (kg0 + 1 <= qg_a) ? s[nt][1] * ATT_SCALE : -1e30f;
                s[nt][2] = (kg0     <= qg_b) ? s[nt][2] * ATT_SCALE : -1e30f;
                s[nt][3] = (kg0 + 1 <= qg_b) ? s[nt][3] * ATT_SCALE : -1e30f;
            }
        } else {
#pragma unroll
            for (int nt = 0; nt < 8; nt++)
#pragma unroll
                for (int r = 0; r < 4; r++) s[nt][r] *= ATT_SCALE;
        }

        float mlA = -INFINITY, mlB = -INFINITY;
#pragma unroll
        for (int nt = 0; nt < 8; nt++) {
            mlA = fmaxf(mlA, fmaxf(s[nt][0], s[nt][1]));
            mlB = fmaxf(mlB, fmaxf(s[nt][2], s[nt][3]));
        }
        mlA = fmaxf(mlA, __shfl_xor_sync(0xffffffffu, mlA, 1));
        mlA = fmaxf(mlA, __shfl_xor_sync(0xffffffffu, mlA, 2));
        mlB = fmaxf(mlB, __shfl_xor_sync(0xffffffffu, mlB, 1));
        mlB = fmaxf(mlB, __shfl_xor_sync(0xffffffffu, mlB, 2));

        float mnA = fmaxf(m_a, mlA), mnB = fmaxf(m_b, mlB);
        float alA = __expf(m_a - mnA), alB = __expf(m_b - mnB);

        float sumA = 0.f, sumB = 0.f;
#pragma unroll
        for (int nt = 0; nt < 8; nt++) {
            float p0 = __expf(s[nt][0] - mnA);
            float p1 = __expf(s[nt][1] - mnA);
            float p2 = __expf(s[nt][2] - mnB);
            float p3 = __expf(s[nt][3] - mnB);
            sumA += p0 + p1;
            sumB += p2 + p3;
            int col = nt * 8 + 2 * t;
            p_s[(mw + g) * ASTR + col]     = f2tf(p0);
            p_s[(mw + g) * ASTR + col + 1] = f2tf(p1);
            p_s[(mw + 8 + g) * ASTR + col]     = f2tf(p2);
            p_s[(mw + 8 + g) * ASTR + col + 1] = f2tf(p3);
        }
        sumA += __shfl_xor_sync(0xffffffffu, sumA, 1);
        sumA += __shfl_xor_sync(0xffffffffu, sumA, 2);
        sumB += __shfl_xor_sync(0xffffffffu, sumB, 1);
        sumB += __shfl_xor_sync(0xffffffffu, sumB, 2);

        l_a = l_a * alA + sumA;  m_a = mnA;
        l_b = l_b * alB + sumB;  m_b = mnB;

#pragma unroll
        for (int nt = 0; nt < 8; nt++) {
            o[nt][0] *= alA; o[nt][1] *= alA;
            o[nt][2] *= alB; o[nt][3] *= alB;
        }

        __syncwarp();

#pragma unroll
        for (int ks = 0; ks < 8; ks++) {
            const int kk = ks * 8;
            unsigned a0 = p_s[(mw + g) * ASTR + kk + t];
            unsigned a1 = p_s[(mw + 8 + g) * ASTR + kk + t];
            unsigned a2 = p_s[(mw + g) * ASTR + kk + 4 + t];
            unsigned a3 = p_s[(mw + 8 + g) * ASTR + kk + 4 + t];
#pragma unroll
            for (int nt = 0; nt < 8; nt++) {
                unsigned b0 = v_s[(nt * 8 + g) * ASTR + kk + t];
                unsigned b1 = v_s[(nt * 8 + g) * ASTR + kk + 4 + t];
                asm volatile(
                    "mma.sync.aligned.m16n8k8.row.col.f32.tf32.tf32.f32 "
                    "{%0,%1,%2,%3}, {%4,%5,%6,%7}, {%8,%9}, {%0,%1,%2,%3};"
                    : "+f"(o[nt][0]), "+f"(o[nt][1]), "+f"(o[nt][2]), "+f"(o[nt][3])
                    : "r"(a0), "r"(a1), "r"(a2), "r"(a3), "r"(b0), "r"(b1));
            }
        }
        __syncthreads();
    }

    float lseA = m_a + logf(l_a);
    float lseB = m_b + logf(l_b);
    float snk  = sinks[h];
    float invA = (1.f / (1.f + __expf(-(lseA - snk)))) / l_a;
    float invB = (1.f / (1.f + __expf(-(lseB - snk)))) / l_b;

#pragma unroll
    for (int nt = 0; nt < 8; nt++) {
        int col = nt * 8 + 2 * t;
        float* oa = &O[qg_a * (NH * HD) + h * HD + col];
        float* ob = &O[qg_b * (NH * HD) + h * HD + col];
        oa[0] = o[nt][0] * invA;
        oa[1] = o[nt][1] * invA;
        ob[0] = o[nt][2] * invB;
        ob[1] = o[nt][3] * invB;
    }
}

// ---------------- launch ----------------------------------------------------
extern "C" void kernel_launch(void* const* d_in, const int* in_sizes, int n_in,
                              void* d_out, int out_size)
{
    const float* x     = (const float*)d_in[0];
    const float* rope  = (const float*)d_in[1];
    const float* wq_w  = (const float*)d_in[2];
    const float* wq_b  = (const float*)d_in[3];
    const float* wk_w  = (const float*)d_in[4];
    const float* wk_b  = (const float*)d_in[5];
    const float* wv_w  = (const float*)d_in[6];
    const float* wv_b  = (const float*)d_in[7];
    const float* wo_w  = (const float*)d_in[8];
    const float* wo_b  = (const float*)d_in[9];
    const float* sinks = (const float*)d_in[10];
    float* out = (float*)d_out;

    float *gq, *gk, *gv, *ga;
    cudaGetSymbolAddress((void**)&gq, g_q);
    cudaGetSymbolAddress((void**)&gk, g_k);
    cudaGetSymbolAddress((void**)&gv, g_v);
    cudaGetSymbolAddress((void**)&ga, g_attn);

    cudaFuncSetAttribute(qkv_gemm, cudaFuncAttributeMaxDynamicSharedMemorySize,
                         GEMM_SMEM);
    cudaFuncSetAttribute(gemm2, cudaFuncAttributeMaxDynamicSharedMemorySize,
                         GEMM_SMEM);

    // Fused QKV projections (tf32 tensor cores, double-buffered cp.async)
    qkv_gemm<<<dim3(24, 16), 256, GEMM_SMEM>>>(x, wq_w, wq_b, gq,
                                               wk_w, wk_b, gk,
                                               wv_w, wv_b, gv);

    // RoPE on Q and K
    {
        int tq = S_LEN * NH * (HD / 2);
        rope_kernel<<<(tq + 255) / 256, 256>>>(gq, rope, NH);
        int tk = S_LEN * NKV * (HD / 2);
        rope_kernel<<<(tk + 255) / 256, 256>>>(gk, rope, NKV);
    }

    // Flash attention (tf32 tensor cores)
    {
        int smem = 4 * 64 * ASTR * (int)sizeof(unsigned);  // 69632 B
        cudaFuncSetAttribute(attn_mma,
                             cudaFuncAttributeMaxDynamicSharedMemorySize, smem);
        attn_mma<<<dim3(S_LEN / 64, NH), 128, smem>>>(gq, gk, gv, sinks, ga);
    }

    // Output projection
    gemm2<<<dim3(16, 16), 256, GEMM_SMEM>>>(ga, wo_w, wo_b, out, DIM, NH * HD);
}

// round 5
// speedup vs baseline: 8.2038x; 1.0515x over previous
#include <cuda_runtime.h>
#include <math.h>

#define S_LEN 2048
#define DIM   2048
#define NH    32
#define NKV   8
#define HD    64
#define NREP  4           // NH / NKV
#define ATT_SCALE 0.125f  // 1/sqrt(64)

// ---------------- scratch (device globals; no allocation allowed) ----------
__device__ float g_q[S_LEN * NH * HD];     // 16 MB
__device__ float g_k[S_LEN * NKV * HD];    // 4 MB
__device__ float g_v[S_LEN * NKV * HD];    // 4 MB
__device__ float g_attn[S_LEN * NH * HD];  // 16 MB

__device__ __forceinline__ unsigned f2tf(float f) {
    unsigned r;
    asm("cvt.rna.tf32.f32 %0, %1;" : "=r"(r) : "f"(f));
    return r;
}

__device__ __forceinline__ void cpasync16(void* smem_ptr, const void* gptr) {
    unsigned s = (unsigned)__cvta_generic_to_shared(smem_ptr);
    asm volatile("cp.async.cg.shared.global [%0], [%1], 16;\n" :: "r"(s), "l"(gptr));
}
__device__ __forceinline__ void cp_commit() {
    asm volatile("cp.async.commit_group;\n");
}
__device__ __forceinline__ void cp_wait0() {
    asm volatile("cp.async.wait_group 0;\n");
}
__device__ __forceinline__ void cp_wait1() {
    asm volatile("cp.async.wait_group 1;\n");
}

// ---------------- TF32 tensor-core GEMM core --------------------------------
// C[M,N] = A[M,K] @ B[N,K]^T + bias[N]
// 128x128 block tile, BK=32, 3-stage cp.async pipeline, 8 warps (2x4),
// warp tile 64x32, mma.m16n8k8.tf32. smem row stride 36 -> fragment LDS
// conflict-free (bank = 4g+t, permutation of 0..31).
#define GSTR  36
#define TILEW (128 * GSTR)   // words per (A or B) tile buffer
#define NSTG  3

__device__ __forceinline__ void gemm_core(
    const float* __restrict__ A, const float* __restrict__ B,
    const float* __restrict__ bias, float* __restrict__ C,
    int N, int K, int m0, int n0, float* sm)
{
    float* As = sm;                        // [NSTG][128][GSTR]
    float* Bs = sm + NSTG * TILEW;         // [NSTG][128][GSTR]

    const int tid  = threadIdx.x;
    const int lane = tid & 31;
    const int w    = tid >> 5;
    const int mw   = (w >> 2) * 64;
    const int nw   = (w & 3) * 32;
    const int g    = lane >> 2;
    const int t    = lane & 3;

    const int lr = tid >> 3;          // 0..31
    const int lc = (tid & 7) << 2;    // 0,4,..28

    float acc[4][4][4];
#pragma unroll
    for (int mt = 0; mt < 4; mt++)
#pragma unroll
        for (int nt = 0; nt < 4; nt++)
#pragma unroll
            for (int r = 0; r < 4; r++) acc[mt][nt][r] = 0.f;

    const int ntiles = K >> 5;

    // ---- prologue: stage 0 and 1 ----
#pragma unroll
    for (int p = 0; p < 2; p++) {
        float* ad = As + p * TILEW;
        float* bd = Bs + p * TILEW;
        const int k0 = p << 5;
#pragma unroll
        for (int i = 0; i < 4; i++) {
            int r = lr + i * 32;
            cpasync16(&ad[r * GSTR + lc], &A[(m0 + r) * K + k0 + lc]);
            cpasync16(&bd[r * GSTR + lc], &B[(n0 + r) * K + k0 + lc]);
        }
        cp_commit();
    }

    int st = 0;
    for (int kt = 0; kt < ntiles; kt++) {
        if (kt + 1 < ntiles) cp_wait1(); else cp_wait0();
        __syncthreads();

        // issue stage kt+2 (overlaps with compute below)
        if (kt + 2 < ntiles) {
            const int k0 = (kt + 2) << 5;
            int sn = st + 2; if (sn >= NSTG) sn -= NSTG;
            float* an = As + sn * TILEW;
            float* bn = Bs + sn * TILEW;
#pragma unroll
            for (int i = 0; i < 4; i++) {
                int r = lr + i * 32;
                cpasync16(&an[r * GSTR + lc], &A[(m0 + r) * K + k0 + lc]);
                cpasync16(&bn[r * GSTR + lc], &B[(n0 + r) * K + k0 + lc]);
            }
            cp_commit();
        }

        const float* ac = As + st * TILEW;
        const float* bc = Bs + st * TILEW;
#pragma unroll
        for (int ks = 0; ks < 4; ks++) {
            const int kk = ks * 8;
            unsigned bf[4][2];
#pragma unroll
            for (int nt = 0; nt < 4; nt++) {
                bf[nt][0] = f2tf(bc[(nw + nt * 8 + g) * GSTR + kk + t]);
                bf[nt][1] = f2tf(bc[(nw + nt * 8 + g) * GSTR + kk + 4 + t]);
            }
#pragma unroll
            for (int mt = 0; mt < 4; mt++) {
                unsigned a0 = f2tf(ac[(mw + mt * 16 + g) * GSTR + kk + t]);
                unsigned a1 = f2tf(ac[(mw + mt * 16 + 8 + g) * GSTR + kk + t]);
                unsigned a2 = f2tf(ac[(mw + mt * 16 + g) * GSTR + kk + 4 + t]);
                unsigned a3 = f2tf(ac[(mw + mt * 16 + 8 + g) * GSTR + kk + 4 + t]);
#pragma unroll
                for (int nt = 0; nt < 4; nt++) {
                    asm volatile(
                        "mma.sync.aligned.m16n8k8.row.col.f32.tf32.tf32.f32 "
                        "{%0,%1,%2,%3}, {%4,%5,%6,%7}, {%8,%9}, {%0,%1,%2,%3};"
                        : "+f"(acc[mt][nt][0]), "+f"(acc[mt][nt][1]),
                          "+f"(acc[mt][nt][2]), "+f"(acc[mt][nt][3])
                        : "r"(a0), "r"(a1), "r"(a2), "r"(a3),
                          "r"(bf[nt][0]), "r"(bf[nt][1]));
                }
            }
        }
        st++; if (st >= NSTG) st = 0;
    }

    // ---- epilogue ----
#pragma unroll
    for (int mt = 0; mt < 4; mt++) {
#pragma unroll
        for (int nt = 0; nt < 4; nt++) {
            int row = m0 + mw + mt * 16 + g;
            int col = n0 + nw + nt * 8 + t * 2;
            float b0 = bias[col], b1 = bias[col + 1];
            C[row * N + col]           = acc[mt][nt][0] + b0;
            C[row * N + col + 1]       = acc[mt][nt][1] + b1;
            C[(row + 8) * N + col]     = acc[mt][nt][2] + b0;
            C[(row + 8) * N + col + 1] = acc[mt][nt][3] + b1;
        }
    }
}

#define GEMM_SMEM (2 * NSTG * TILEW * (int)sizeof(float))   // 110592 B

__global__ void __launch_bounds__(256)
qkv_gemm(const float* __restrict__ x,
         const float* __restrict__ wq, const float* __restrict__ bq, float* __restrict__ oq,
         const float* __restrict__ wk, const float* __restrict__ bk, float* __restrict__ ok,
         const float* __restrict__ wv, const float* __restrict__ bv, float* __restrict__ ov)
{
    extern __shared__ float sm[];
    const int bx = blockIdx.x;
    const float *B, *bias; float* C; int N, n0;
    if (bx < 16)      { B = wq; bias = bq; C = oq; N = 2048; n0 = bx * 128; }
    else if (bx < 20) { B = wk; bias = bk; C = ok; N = 512;  n0 = (bx - 16) * 128; }
    else              { B = wv; bias = bv; C = ov; N = 512;  n0 = (bx - 20) * 128; }
    gemm_core(x, B, bias, C, N, DIM, blockIdx.y * 128, n0, sm);
}

__global__ void __launch_bounds__(256)
gemm2(const float* __restrict__ A, const float* __restrict__ B,
      const float* __restrict__ bias, float* __restrict__ C, int N, int K)
{
    extern __shared__ float sm[];
    gemm_core(A, B, bias, C, N, K, blockIdx.y * 128, blockIdx.x * 128, sm);
}

// ---------------- RoPE (in place) ------------------------------------------
__global__ void rope_kernel(float* __restrict__ t, const float* __restrict__ rope,
                            int heads)
{
    int idx = blockIdx.x * blockDim.x + threadIdx.x;
    int total = S_LEN * heads * (HD / 2);
    if (idx >= total) return;
    int i = idx % (HD / 2);
    int h = (idx / (HD / 2)) % heads;
    int s = idx / (heads * (HD / 2));
    float c  = rope[s * HD + i];
    float sn = rope[s * HD + HD / 2 + i];
    float* p = t + (s * heads + h) * HD;
    float x1 = p[i], x2 = p[i + HD / 2];
    p[i]           = x1 * c  - x2 * sn;
    p[i + HD / 2]  = x1 * sn + x2 * c;
}

// ---------------- Tensor-core flash attention v2 (tf32 mma) -----------------
// BQ=128, BKV=64. 4 warps, each owns 32 query rows (2 m-tiles of 16).
// 1.5 LDS per mma. V stored transposed with conflict-free STS.
#define ASTR 68
#define ATT_BQ 128

__global__ void __launch_bounds__(128)
attn_mma(const float* __restrict__ Q, const float* __restrict__ K,
         const float* __restrict__ V, const float* __restrict__ sinks,
         float* __restrict__ O)
{
    extern __shared__ unsigned sm_u[];
    unsigned* q_s = sm_u;                   // [128][ASTR]
    unsigned* k_s = q_s + 128 * ASTR;       // [64][ASTR]
    unsigned* v_s = k_s + 64 * ASTR;        // [64][ASTR] transposed: [dim][key]
    unsigned* p_s = v_s + 64 * ASTR;        // [128][ASTR]

    const int h    = blockIdx.y;
    const int q0   = blockIdx.x * ATT_BQ;
    const int kvh  = h >> 2;                // h / NREP
    const int tid  = threadIdx.x;
    const int lane = tid & 31;
    const int w    = tid >> 5;
    const int g    = lane >> 2;
    const int t    = lane & 3;
    const int mw   = w * 32;                // warp's 32 query rows

    // ---- load Q tile (128 rows x 64 dims) ----
#pragma unroll
    for (int i = 0; i < 16; i++) {
        int idx = tid + i * 128;
        int row = idx >> 4, c4 = (idx & 15) << 2;
        float4 v4 = *(const float4*)&Q[(q0 + row) * (NH * HD) + h * HD + c4];
        q_s[row * ASTR + c4 + 0] = f2tf(v4.x);
        q_s[row * ASTR + c4 + 1] = f2tf(v4.y);
        q_s[row * ASTR + c4 + 2] = f2tf(v4.z);
        q_s[row * ASTR + c4 + 3] = f2tf(v4.w);
    }

    float o[2][8][4];
#pragma unroll
    for (int mt = 0; mt < 2; mt++)
#pragma unroll
        for (int nt = 0; nt < 8; nt++)
#pragma unroll
            for (int r = 0; r < 4; r++) o[mt][nt][r] = 0.f;
    float m_st[2][2], l_st[2][2];
#pragma unroll
    for (int mt = 0; mt < 2; mt++) {
        m_st[mt][0] = -INFINITY; m_st[mt][1] = -INFINITY;
        l_st[mt][0] = 0.f;       l_st[mt][1] = 0.f;
    }

    __syncthreads();

    for (int k0 = 0; k0 < q0 + ATT_BQ; k0 += 64) {
        // ---- K: coalesced load + natural store ----
#pragma unroll
        for (int i = 0; i < 8; i++) {
            int idx = tid + i * 128;
            int row = idx >> 4, c4 = (idx & 15) << 2;
            float4 k4 = *(const float4*)&K[(k0 + row) * (NKV * HD) + kvh * HD + c4];
            k_s[row * ASTR + c4 + 0] = f2tf(k4.x);
            k_s[row * ASTR + c4 + 1] = f2tf(k4.y);
            k_s[row * ASTR + c4 + 2] = f2tf(k4.z);
            k_s[row * ASTR + c4 + 3] = f2tf(k4.w);
        }
        // ---- V: key-contiguous mapping -> conflict-free transposed STS ----
#pragma unroll
        for (int i = 0; i < 8; i++) {
            int idx = tid + i * 128;
            int row = idx & 63;            // key index (contiguous in tid)
            int c4  = (idx >> 6) << 2;     // dim base
            float4 v4 = *(const float4*)&V[(k0 + row) * (NKV * HD) + kvh * HD + c4];
            v_s[(c4 + 0) * ASTR + row] = f2tf(v4.x);
            v_s[(c4 + 1) * ASTR + row] = f2tf(v4.y);
            v_s[(c4 + 2) * ASTR + row] = f2tf(v4.z);
            v_s[(c4 + 3) * ASTR + row] = f2tf(v4.w);
        }
        __syncthreads();

        // ---- S = Q @ K^T (32 rows x 64 keys per warp) ----
        float s[2][8][4];
#pragma unroll
        for (int mt = 0; mt < 2; mt++)
#pragma unroll
            for (int nt = 0; nt < 8; nt++)
#pragma unroll
                for (int r = 0; r < 4; r++) s[mt][nt][r] = 0.f;

#pragma unroll
        for (int ks = 0; ks < 8; ks++) {
            const int kk = ks * 8;
            unsigned a[2][4];
#pragma unroll
            for (int mt = 0; mt < 2; mt++) {
                const int rb = (mw + mt * 16 + g) * ASTR;
                a[mt][0] = q_s[rb + kk + t];
                a[mt][1] = q_s[rb + 8 * ASTR + kk + t];
                a[mt][2] = q_s[rb + kk + 4 + t];
                a[mt][3] = q_s[rb + 8 * ASTR + kk + 4 + t];
            }
#pragma unroll
            for (int nt = 0; nt < 8; nt++) {
                unsigned b0 = k_s[(nt * 8 + g) * ASTR + kk + t];
                unsigned b1 = k_s[(nt * 8 + g) * ASTR + kk + 4 + t];
#pragma unroll
                for (int mt = 0; mt < 2; mt++) {
                    asm volatile(
                        "mma.sync.aligned.m16n8k8.row.col.f32.tf32.tf32.f32 "
                        "{%0,%1,%2,%3}, {%4,%5,%6,%7}, {%8,%9}, {%0,%1,%2,%3};"
                        : "+f"(s[mt][nt][0]), "+f"(s[mt][nt][1]),
                          "+f"(s[mt][nt][2]), "+f"(s[mt][nt][3])
                        : "r"(a[mt][0]), "r"(a[mt][1]), "r"(a[mt][2]), "r"(a[mt][3]),
                          "r"(b0), "r"(b1));
                }
            }
        }

        // ---- scale + causal mask ----
        if (k0 >= q0) {
#pragma unroll
            for (int mt = 0; mt < 2; mt++) {
                int qa = q0 + mw + mt * 16 + g;
                int qb = qa + 8;
#pragma unroll
                for (int nt = 0; nt < 8; nt++) {
                    int kg0 = k0 + nt * 8 + 2 * t;
                    s[mt][nt][0] = (kg0     <= qa) ? s[mt][nt][0] * ATT_SCALE : -1e30f;
                    s[mt][nt][1] = (kg0 + 1 <= qa) ? s[mt][nt][1] * ATT_SCALE : -1e30f;
                    s[mt][nt][2] = (kg0     <= qb) ? s[mt][nt][2] * ATT_SCALE : -1e30f;
                    s[mt][nt][3] = (kg0 + 1 <= qb) ? s[mt][nt][3] * ATT_SCALE : -1e30f;
                }
            }
        } else {
#pragma unroll
            for (int mt = 0; mt < 2; mt++)
#pragma unroll
                for (int nt = 0; nt < 8; nt++)
#pragma unroll
                    for (int r = 0; r < 4; r++) s[mt][nt][r] *= ATT_SCALE;
        }

        // ---- online softmax ----
#pragma unroll
        for (int mt = 0; mt < 2; mt++) {
            float mlA = -INFINITY, mlB = -INFINITY;
#pragma unroll
            for (int nt = 0; nt < 8; nt++) {
                mlA = fmaxf(mlA, fmaxf(s[mt][nt][0], s[mt][nt][1]));
                mlB = fmaxf(mlB, fmaxf(s[mt][nt][2], s[mt][nt][3]));
            }
            mlA = fmaxf(mlA, __shfl_xor_sync(0xffffffffu, mlA, 1));
            mlA = fmaxf(mlA, __shfl_xor_sync(0xffffffffu, mlA, 2));
            mlB = fmaxf(mlB, __shfl_xor_sync(0xffffffffu, mlB, 1));
            mlB = fmaxf(mlB, __shfl_xor_sync(0xffffffffu, mlB, 2));

            float mnA = fmaxf(m_st[mt][0], mlA);
            float mnB = fmaxf(m_st[mt][1], mlB);
            float alA = __expf(m_st[mt][0] - mnA);
            float alB = __expf(m_st[mt][1] - mnB);

            float sumA = 0.f, sumB = 0.f;
            const int rbA = (mw + mt * 16 + g) * ASTR;
            const int rbB = rbA + 8 * ASTR;
#pragma unroll
            for (int nt = 0; nt < 8; nt++) {
                float p0 = __expf(s[mt][nt][0] - mnA);
                float p1 = __expf(s[mt][nt][1] - mnA);
                float p2 = __expf(s[mt][nt][2] - mnB);
                float p3 = __expf(s[mt][nt][3] - mnB);
                sumA += p0 + p1;
                sumB += p2 + p3;
                int col = nt * 8 + 2 * t;
                uint2 ua = make_uint2(f2tf(p0), f2tf(p1));
                uint2 ub = make_uint2(f2tf(p2), f2tf(p3));
                *(uint2*)&p_s[rbA + col] = ua;
                *(uint2*)&p_s[rbB + col] = ub;
            }
            sumA += __shfl_xor_sync(0xffffffffu, sumA, 1);
            sumA += __shfl_xor_sync(0xffffffffu, sumA, 2);
            sumB += __shfl_xor_sync(0xffffffffu, sumB, 1);
            sumB += __shfl_xor_sync(0xffffffffu, sumB, 2);

            l_st[mt][0] = l_st[mt][0] * alA + sumA;  m_st[mt][0] = mnA;
            l_st[mt][1] = l_st[mt][1] * alB + sumB;  m_st[mt][1] = mnB;

#pragma unroll
            for (int nt = 0; nt < 8; nt++) {
                o[mt][nt][0] *= alA; o[mt][nt][1] *= alA;
                o[mt][nt][2] *= alB; o[mt][nt][3] *= alB;
            }
        }

        __syncwarp();   // p_s rows private to this warp

        // ---- O += P @ V ----
#pragma unroll
        for (int ks = 0; ks < 8; ks++) {
            const int kk = ks * 8;
            unsigned a[2][4];
#pragma unroll
            for (int mt = 0; mt < 2; mt++) {
                const int rb = (mw + mt * 16 + g) * ASTR;
                a[mt][0] = p_s[rb + kk + t];
                a[mt][1] = p_s[rb + 8 * ASTR + kk + t];
                a[mt][2] = p_s[rb + kk + 4 + t];
                a[mt][3] = p_s[rb + 8 * ASTR + kk + 4 + t];
            }
#pragma unroll
            for (int nt = 0; nt < 8; nt++) {
                unsigned b0 = v_s[(nt * 8 + g) * ASTR + kk + t];
                unsigned b1 = v_s[(nt * 8 + g) * ASTR + kk + 4 + t];
#pragma unroll
                for (int mt = 0; mt < 2; mt++) {
                    asm volatile(
                        "mma.sync.aligned.m16n8k8.row.col.f32.tf32.tf32.f32 "
                        "{%0,%1,%2,%3}, {%4,%5,%6,%7}, {%8,%9}, {%0,%1,%2,%3};"
                        : "+f"(o[mt][nt][0]), "+f"(o[mt][nt][1]),
                          "+f"(o[mt][nt][2]), "+f"(o[mt][nt][3])
                        : "r"(a[mt][0]), "r"(a[mt][1]), "r"(a[mt][2]), "r"(a[mt][3]),
                          "r"(b0), "r"(b1));
                }
            }
        }
        __syncthreads();
    }

    // ---- epilogue: normalize + sink scale ----
    float snk = sinks[h];
#pragma unroll
    for (int mt = 0; mt < 2; mt++) {
        int qa = q0 + mw + mt * 16 + g;
        int qb = qa + 8;
        float lseA = m_st[mt][0] + logf(l_st[mt][0]);
        float lseB = m_st[mt][1] + logf(l_st[mt][1]);
        float invA = (1.f / (1.f + __expf(-(lseA - snk)))) / l_st[mt][0];
        float invB = (1.f / (1.f + __expf(-(lseB - snk)))) / l_st[mt][1];
#pragma unroll
        for (int nt = 0; nt < 8; nt++) {
            int col = nt * 8 + 2 * t;
            float2 fa = make_float2(o[mt][nt][0] * invA, o[mt][nt][1] * invA);
            float2 fb = make_float2(o[mt][nt][2] * invB, o[mt][nt][3] * invB);
            *(float2*)&O[qa * (NH * HD) + h * HD + col] = fa;
            *(float2*)&O[qb * (NH * HD) + h * HD + col] = fb;
        }
    }
}

#define ATT_SMEM ((128 + 64 + 64 + 128) * ASTR * (int)sizeof(unsigned))  // 104448

// ---------------- launch ----------------------------------------------------
extern "C" void kernel_launch(void* const* d_in, const int* in_sizes, int n_in,
                              void* d_out, int out_size)
{
    const float* x     = (const float*)d_in[0];
    const float* rope  = (const float*)d_in[1];
    const float* wq_w  = (const float*)d_in[2];
    const float* wq_b  = (const float*)d_in[3];
    const float* wk_w  = (const float*)d_in[4];
    const float* wk_b  = (const float*)d_in[5];
    const float* wv_w  = (const float*)d_in[6];
    const float* wv_b  = (const float*)d_in[7];
    const float* wo_w  = (const float*)d_in[8];
    const float* wo_b  = (const float*)d_in[9];
    const float* sinks = (const float*)d_in[10];
    float* out = (float*)d_out;

    float *gq, *gk, *gv, *ga;
    cudaGetSymbolAddress((void**)&gq, g_q);
    cudaGetSymbolAddress((void**)&gk, g_k);
    cudaGetSymbolAddress((void**)&gv, g_v);
    cudaGetSymbolAddress((void**)&ga, g_attn);

    cudaFuncSetAttribute(qkv_gemm, cudaFuncAttributeMaxDynamicSharedMemorySize,
                         GEMM_SMEM);
    cudaFuncSetAttribute(gemm2, cudaFuncAttributeMaxDynamicSharedMemorySize,
                         GEMM_SMEM);
    cudaFuncSetAttribute(attn_mma, cudaFuncAttributeMaxDynamicSharedMemorySize,
                         ATT_SMEM);

    // Fused QKV projections
    qkv_gemm<<<dim3(24, 16), 256, GEMM_SMEM>>>(x, wq_w, wq_b, gq,
                                               wk_w, wk_b, gk,
                                               wv_w, wv_b, gv);

    // RoPE on Q and K
    {
        int tq = S_LEN * NH * (HD / 2);
        rope_kernel<<<(tq + 255) / 256, 256>>>(gq, rope, NH);
        int tk = S_LEN * NKV * (HD / 2);
        rope_kernel<<<(tk + 255) / 256, 256>>>(gk, rope, NKV);
    }

    // Flash attention
    attn_mma<<<dim3(S_LEN / ATT_BQ, NH), 128, ATT_SMEM>>>(gq, gk, gv, sinks, ga);

    // Output projection
    gemm2<<<dim3(16, 16), 256, GEMM_SMEM>>>(ga, wo_w, wo_b, out, DIM, NH * HD);
}

// round 6
// speedup vs baseline: 8.3199x; 1.0142x over previous
#include <cuda_runtime.h>
#include <math.h>

#define S_LEN 2048
#define DIM   2048
#define NH    32
#define NKV   8
#define HD    64
#define NREP  4           // NH / NKV
#define ATT_SCALE 0.125f  // 1/sqrt(64)

// ---------------- scratch (device globals; no allocation allowed) ----------
__device__ float g_q[S_LEN * NH * HD];     // 16 MB
__device__ float g_k[S_LEN * NKV * HD];    // 4 MB
__device__ float g_v[S_LEN * NKV * HD];    // 4 MB
__device__ float g_attn[S_LEN * NH * HD];  // 16 MB

__device__ __forceinline__ unsigned f2tf(float f) {
    unsigned r;
    asm("cvt.rna.tf32.f32 %0, %1;" : "=r"(r) : "f"(f));
    return r;
}

__device__ __forceinline__ void cpasync16(void* smem_ptr, const void* gptr) {
    unsigned s = (unsigned)__cvta_generic_to_shared(smem_ptr);
    asm volatile("cp.async.cg.shared.global [%0], [%1], 16;\n" :: "r"(s), "l"(gptr));
}
__device__ __forceinline__ void cp_commit() {
    asm volatile("cp.async.commit_group;\n");
}
__device__ __forceinline__ void cp_wait0() {
    asm volatile("cp.async.wait_group 0;\n");
}
__device__ __forceinline__ void cp_wait1() {
    asm volatile("cp.async.wait_group 1;\n");
}

// ---------------- TF32 tensor-core GEMM core --------------------------------
#define GSTR  36
#define TILEW (128 * GSTR)
#define NSTG  3

__device__ __forceinline__ void gemm_core(
    const float* __restrict__ A, const float* __restrict__ B,
    const float* __restrict__ bias, float* __restrict__ C,
    int N, int K, int m0, int n0, float* sm)
{
    float* As = sm;
    float* Bs = sm + NSTG * TILEW;

    const int tid  = threadIdx.x;
    const int lane = tid & 31;
    const int w    = tid >> 5;
    const int mw   = (w >> 2) * 64;
    const int nw   = (w & 3) * 32;
    const int g    = lane >> 2;
    const int t    = lane & 3;

    const int lr = tid >> 3;
    const int lc = (tid & 7) << 2;

    float acc[4][4][4];
#pragma unroll
    for (int mt = 0; mt < 4; mt++)
#pragma unroll
        for (int nt = 0; nt < 4; nt++)
#pragma unroll
            for (int r = 0; r < 4; r++) acc[mt][nt][r] = 0.f;

    const int ntiles = K >> 5;

#pragma unroll
    for (int p = 0; p < 2; p++) {
        float* ad = As + p * TILEW;
        float* bd = Bs + p * TILEW;
        const int k0 = p << 5;
#pragma unroll
        for (int i = 0; i < 4; i++) {
            int r = lr + i * 32;
            cpasync16(&ad[r * GSTR + lc], &A[(m0 + r) * K + k0 + lc]);
            cpasync16(&bd[r * GSTR + lc], &B[(n0 + r) * K + k0 + lc]);
        }
        cp_commit();
    }

    int st = 0;
    for (int kt = 0; kt < ntiles; kt++) {
        if (kt + 1 < ntiles) cp_wait1(); else cp_wait0();
        __syncthreads();

        if (kt + 2 < ntiles) {
            const int k0 = (kt + 2) << 5;
            int sn = st + 2; if (sn >= NSTG) sn -= NSTG;
            float* an = As + sn * TILEW;
            float* bn = Bs + sn * TILEW;
#pragma unroll
            for (int i = 0; i < 4; i++) {
                int r = lr + i * 32;
                cpasync16(&an[r * GSTR + lc], &A[(m0 + r) * K + k0 + lc]);
                cpasync16(&bn[r * GSTR + lc], &B[(n0 + r) * K + k0 + lc]);
            }
            cp_commit();
        }

        const float* ac = As + st * TILEW;
        const float* bc = Bs + st * TILEW;
#pragma unroll
        for (int ks = 0; ks < 4; ks++) {
            const int kk = ks * 8;
            unsigned bf[4][2];
#pragma unroll
            for (int nt = 0; nt < 4; nt++) {
                bf[nt][0] = f2tf(bc[(nw + nt * 8 + g) * GSTR + kk + t]);
                bf[nt][1] = f2tf(bc[(nw + nt * 8 + g) * GSTR + kk + 4 + t]);
            }
#pragma unroll
            for (int mt = 0; mt < 4; mt++) {
                unsigned a0 = f2tf(ac[(mw + mt * 16 + g) * GSTR + kk + t]);
                unsigned a1 = f2tf(ac[(mw + mt * 16 + 8 + g) * GSTR + kk + t]);
                unsigned a2 = f2tf(ac[(mw + mt * 16 + g) * GSTR + kk + 4 + t]);
                unsigned a3 = f2tf(ac[(mw + mt * 16 + 8 + g) * GSTR + kk + 4 + t]);
#pragma unroll
                for (int nt = 0; nt < 4; nt++) {
                    asm volatile(
                        "mma.sync.aligned.m16n8k8.row.col.f32.tf32.tf32.f32 "
                        "{%0,%1,%2,%3}, {%4,%5,%6,%7}, {%8,%9}, {%0,%1,%2,%3};"
                        : "+f"(acc[mt][nt][0]), "+f"(acc[mt][nt][1]),
                          "+f"(acc[mt][nt][2]), "+f"(acc[mt][nt][3])
                        : "r"(a0), "r"(a1), "r"(a2), "r"(a3),
                          "r"(bf[nt][0]), "r"(bf[nt][1]));
                }
            }
        }
        st++; if (st >= NSTG) st = 0;
    }

#pragma unroll
    for (int mt = 0; mt < 4; mt++) {
#pragma unroll
        for (int nt = 0; nt < 4; nt++) {
            int row = m0 + mw + mt * 16 + g;
            int col = n0 + nw + nt * 8 + t * 2;
            float b0 = bias[col], b1 = bias[col + 1];
            C[row * N + col]           = acc[mt][nt][0] + b0;
            C[row * N + col + 1]       = acc[mt][nt][1] + b1;
            C[(row + 8) * N + col]     = acc[mt][nt][2] + b0;
            C[(row + 8) * N + col + 1] = acc[mt][nt][3] + b1;
        }
    }
}

#define GEMM_SMEM (2 * NSTG * TILEW * (int)sizeof(float))   // 110592 B

__global__ void __launch_bounds__(256)
qkv_gemm(const float* __restrict__ x,
         const float* __restrict__ wq, const float* __restrict__ bq, float* __restrict__ oq,
         const float* __restrict__ wk, const float* __restrict__ bk, float* __restrict__ ok,
         const float* __restrict__ wv, const float* __restrict__ bv, float* __restrict__ ov)
{
    extern __shared__ float sm[];
    const int bx = blockIdx.x;
    const float *B, *bias; float* C; int N, n0;
    if (bx < 16)      { B = wq; bias = bq; C = oq; N = 2048; n0 = bx * 128; }
    else if (bx < 20) { B = wk; bias = bk; C = ok; N = 512;  n0 = (bx - 16) * 128; }
    else              { B = wv; bias = bv; C = ov; N = 512;  n0 = (bx - 20) * 128; }
    gemm_core(x, B, bias, C, N, DIM, blockIdx.y * 128, n0, sm);
}

__global__ void __launch_bounds__(256)
gemm2(const float* __restrict__ A, const float* __restrict__ B,
      const float* __restrict__ bias, float* __restrict__ C, int N, int K)
{
    extern __shared__ float sm[];
    gemm_core(A, B, bias, C, N, K, blockIdx.y * 128, blockIdx.x * 128, sm);
}

// ---------------- RoPE (in place) ------------------------------------------
__global__ void rope_kernel(float* __restrict__ t, const float* __restrict__ rope,
                            int heads)
{
    int idx = blockIdx.x * blockDim.x + threadIdx.x;
    int total = S_LEN * heads * (HD / 2);
    if (idx >= total) return;
    int i = idx % (HD / 2);
    int h = (idx / (HD / 2)) % heads;
    int s = idx / (heads * (HD / 2));
    float c  = rope[s * HD + i];
    float sn = rope[s * HD + HD / 2 + i];
    float* p = t + (s * heads + h) * HD;
    float x1 = p[i], x2 = p[i + HD / 2];
    p[i]           = x1 * c  - x2 * sn;
    p[i + HD / 2]  = x1 * sn + x2 * c;
}

// ---------------- Flash attention v3: 8 warps, split-KV ---------------------
// BQ=128, BKV=128. Warp (wq, wk): 32 q-rows (wq), 64-key half (wk).
// Per-warp independent online softmax over disjoint key sets; split-KV
// merge in epilogue through smem. 2 warps/SMSP for latency hiding.
#define ASTR 68     // q_s, k_s row stride (words)
#define VSTR 132    // v_s (transposed) & p_s row stride (words)
#define ATT_BQ 128

__global__ void __launch_bounds__(256)
attn_mma(const float* __restrict__ Q, const float* __restrict__ K,
         const float* __restrict__ V, const float* __restrict__ sinks,
         float* __restrict__ O)
{
    extern __shared__ unsigned sm_u[];
    unsigned* q_s = sm_u;                   // [128][ASTR]
    unsigned* k_s = q_s + 128 * ASTR;       // [128][ASTR]
    unsigned* v_s = k_s + 128 * ASTR;       // [64][VSTR]  transposed: [dim][key]
    unsigned* p_s = v_s + 64 * VSTR;        // [128][VSTR]

    const int h    = blockIdx.y;
    const int q0   = blockIdx.x * ATT_BQ;
    const int kvh  = h >> 2;                // h / NREP
    const int tid  = threadIdx.x;
    const int lane = tid & 31;
    const int w    = tid >> 5;
    const int g    = lane >> 2;
    const int t    = lane & 3;
    const int wq   = w & 3;                 // q-row group
    const int wk   = w >> 2;                // key half
    const int mw   = wq * 32;
    const int kvo  = wk * 64;               // key offset within 128-key tile

    // ---- load Q tile (128 rows x 64 dims) ----
#pragma unroll
    for (int i = 0; i < 8; i++) {
        int idx = tid + i * 256;
        int row = idx >> 4, c4 = (idx & 15) << 2;
        float4 v4 = *(const float4*)&Q[(q0 + row) * (NH * HD) + h * HD + c4];
        q_s[row * ASTR + c4 + 0] = f2tf(v4.x);
        q_s[row * ASTR + c4 + 1] = f2tf(v4.y);
        q_s[row * ASTR + c4 + 2] = f2tf(v4.z);
        q_s[row * ASTR + c4 + 3] = f2tf(v4.w);
    }

    float o[2][8][4];
#pragma unroll
    for (int mt = 0; mt < 2; mt++)
#pragma unroll
        for (int nt = 0; nt < 8; nt++)
#pragma unroll
            for (int r = 0; r < 4; r++) o[mt][nt][r] = 0.f;
    float m_st[2][2], l_st[2][2];
#pragma unroll
    for (int mt = 0; mt < 2; mt++) {
        m_st[mt][0] = -INFINITY; m_st[mt][1] = -INFINITY;
        l_st[mt][0] = 0.f;       l_st[mt][1] = 0.f;
    }

    __syncthreads();

    for (int k0 = 0; k0 <= q0; k0 += 128) {
        // ---- K tile (128 keys x 64 dims), coalesced ----
#pragma unroll
        for (int i = 0; i < 8; i++) {
            int idx = tid + i * 256;
            int row = idx >> 4, c4 = (idx & 15) << 2;
            float4 k4 = *(const float4*)&K[(k0 + row) * (NKV * HD) + kvh * HD + c4];
            k_s[row * ASTR + c4 + 0] = f2tf(k4.x);
            k_s[row * ASTR + c4 + 1] = f2tf(k4.y);
            k_s[row * ASTR + c4 + 2] = f2tf(k4.z);
            k_s[row * ASTR + c4 + 3] = f2tf(k4.w);
        }
        // ---- V tile transposed: key-contiguous mapping, conflict-free STS --
#pragma unroll
        for (int i = 0; i < 8; i++) {
            int idx = tid + i * 256;
            int row = idx & 127;           // key
            int c4  = (idx >> 7) << 2;     // dim base
            float4 v4 = *(const float4*)&V[(k0 + row) * (NKV * HD) + kvh * HD + c4];
            v_s[(c4 + 0) * VSTR + row] = f2tf(v4.x);
            v_s[(c4 + 1) * VSTR + row] = f2tf(v4.y);
            v_s[(c4 + 2) * VSTR + row] = f2tf(v4.z);
            v_s[(c4 + 3) * VSTR + row] = f2tf(v4.w);
        }
        __syncthreads();

        // ---- S = Q @ K^T (warp: 32 rows x its 64 keys) ----
        float s[2][8][4];
#pragma unroll
        for (int mt = 0; mt < 2; mt++)
#pragma unroll
            for (int nt = 0; nt < 8; nt++)
#pragma unroll
                for (int r = 0; r < 4; r++) s[mt][nt][r] = 0.f;

#pragma unroll
        for (int ks = 0; ks < 8; ks++) {
            const int kk = ks * 8;
            unsigned a[2][4];
#pragma unroll
            for (int mt = 0; mt < 2; mt++) {
                const int rb = (mw + mt * 16 + g) * ASTR;
                a[mt][0] = q_s[rb + kk + t];
                a[mt][1] = q_s[rb + 8 * ASTR + kk + t];
                a[mt][2] = q_s[rb + kk + 4 + t];
                a[mt][3] = q_s[rb + 8 * ASTR + kk + 4 + t];
            }
#pragma unroll
            for (int nt = 0; nt < 8; nt++) {
                unsigned b0 = k_s[(kvo + nt * 8 + g) * ASTR + kk + t];
                unsigned b1 = k_s[(kvo + nt * 8 + g) * ASTR + kk + 4 + t];
#pragma unroll
                for (int mt = 0; mt < 2; mt++) {
                    asm volatile(
                        "mma.sync.aligned.m16n8k8.row.col.f32.tf32.tf32.f32 "
                        "{%0,%1,%2,%3}, {%4,%5,%6,%7}, {%8,%9}, {%0,%1,%2,%3};"
                        : "+f"(s[mt][nt][0]), "+f"(s[mt][nt][1]),
                          "+f"(s[mt][nt][2]), "+f"(s[mt][nt][3])
                        : "r"(a[mt][0]), "r"(a[mt][1]), "r"(a[mt][2]), "r"(a[mt][3]),
                          "r"(b0), "r"(b1));
                }
            }
        }

        // ---- scale + causal mask (diagonal tile only) ----
        if (k0 == q0) {
#pragma unroll
            for (int mt = 0; mt < 2; mt++) {
                int qa = q0 + mw + mt * 16 + g;
                int qb = qa + 8;
#pragma unroll
                for (int nt = 0; nt < 8; nt++) {
                    int kg0 = k0 + kvo + nt * 8 + 2 * t;
                    s[mt][nt][0] = (kg0     <= qa) ? s[mt][nt][0] * ATT_SCALE : -1e30f;
                    s[mt][nt][1] = (kg0 + 1 <= qa) ? s[mt][nt][1] * ATT_SCALE : -1e30f;
                    s[mt][nt][2] = (kg0     <= qb) ? s[mt][nt][2] * ATT_SCALE : -1e30f;
                    s[mt][nt][3] = (kg0 + 1 <= qb) ? s[mt][nt][3] * ATT_SCALE : -1e30f;
                }
            }
        } else {
#pragma unroll
            for (int mt = 0; mt < 2; mt++)
#pragma unroll
                for (int nt = 0; nt < 8; nt++)
#pragma unroll
                    for (int r = 0; r < 4; r++) s[mt][nt][r] *= ATT_SCALE;
        }

        // ---- per-warp online softmax over its key half ----
#pragma unroll
        for (int mt = 0; mt < 2; mt++) {
            float mlA = -INFINITY, mlB = -INFINITY;
#pragma unroll
            for (int nt = 0; nt < 8; nt++) {
                mlA = fmaxf(mlA, fmaxf(s[mt][nt][0], s[mt][nt][1]));
                mlB = fmaxf(mlB, fmaxf(s[mt][nt][2], s[mt][nt][3]));
            }
            mlA = fmaxf(mlA, __shfl_xor_sync(0xffffffffu, mlA, 1));
            mlA = fmaxf(mlA, __shfl_xor_sync(0xffffffffu, mlA, 2));
            mlB = fmaxf(mlB, __shfl_xor_sync(0xffffffffu, mlB, 1));
            mlB = fmaxf(mlB, __shfl_xor_sync(0xffffffffu, mlB, 2));

            float mnA = fmaxf(m_st[mt][0], mlA);
            float mnB = fmaxf(m_st[mt][1], mlB);
            float alA = __expf(m_st[mt][0] - mnA);
            float alB = __expf(m_st[mt][1] - mnB);

            float sumA = 0.f, sumB = 0.f;
            const int rbA = (mw + mt * 16 + g) * VSTR + kvo;
            const int rbB = rbA + 8 * VSTR;
#pragma unroll
            for (int nt = 0; nt < 8; nt++) {
                float p0 = __expf(s[mt][nt][0] - mnA);
                float p1 = __expf(s[mt][nt][1] - mnA);
                float p2 = __expf(s[mt][nt][2] - mnB);
                float p3 = __expf(s[mt][nt][3] - mnB);
                sumA += p0 + p1;
                sumB += p2 + p3;
                int col = nt * 8 + 2 * t;
                *(uint2*)&p_s[rbA + col] = make_uint2(f2tf(p0), f2tf(p1));
                *(uint2*)&p_s[rbB + col] = make_uint2(f2tf(p2), f2tf(p3));
            }
            sumA += __shfl_xor_sync(0xffffffffu, sumA, 1);
            sumA += __shfl_xor_sync(0xffffffffu, sumA, 2);
            sumB += __shfl_xor_sync(0xffffffffu, sumB, 1);
            sumB += __shfl_xor_sync(0xffffffffu, sumB, 2);

            l_st[mt][0] = l_st[mt][0] * alA + sumA;  m_st[mt][0] = mnA;
            l_st[mt][1] = l_st[mt][1] * alB + sumB;  m_st[mt][1] = mnB;

#pragma unroll
            for (int nt = 0; nt < 8; nt++) {
                o[mt][nt][0] *= alA; o[mt][nt][1] *= alA;
                o[mt][nt][2] *= alB; o[mt][nt][3] *= alB;
            }
        }

        __syncwarp();   // p_s block private to this warp

        // ---- O += P @ V (warp's 64 keys) ----
#pragma unroll
        for (int ks = 0; ks < 8; ks++) {
            const int kk = ks * 8;
            unsigned a[2][4];
#pragma unroll
            for (int mt = 0; mt < 2; mt++) {
                const int rb = (mw + mt * 16 + g) * VSTR + kvo;
                a[mt][0] = p_s[rb + kk + t];
                a[mt][1] = p_s[rb + 8 * VSTR + kk + t];
                a[mt][2] = p_s[rb + kk + 4 + t];
                a[mt][3] = p_s[rb + 8 * VSTR + kk + 4 + t];
            }
#pragma unroll
            for (int nt = 0; nt < 8; nt++) {
                unsigned b0 = v_s[(nt * 8 + g) * VSTR + kvo + kk + t];
                unsigned b1 = v_s[(nt * 8 + g) * VSTR + kvo + kk + 4 + t];
#pragma unroll
                for (int mt = 0; mt < 2; mt++) {
                    asm volatile(
                        "mma.sync.aligned.m16n8k8.row.col.f32.tf32.tf32.f32 "
                        "{%0,%1,%2,%3}, {%4,%5,%6,%7}, {%8,%9}, {%0,%1,%2,%3};"
                        : "+f"(o[mt][nt][0]), "+f"(o[mt][nt][1]),
                          "+f"(o[mt][nt][2]), "+f"(o[mt][nt][3])
                        : "r"(a[mt][0]), "r"(a[mt][1]), "r"(a[mt][2]), "r"(a[mt][3]),
                          "r"(b0), "r"(b1));
                }
            }
        }
        __syncthreads();
    }

    // ---- split-KV merge (pairs: warp w (wk=0) with warp w+4 (wk=1)) ----
    float* ost = (float*)k_s;   // staging: [128][ASTR] unnormalized O from wk=1
    float* mst = (float*)v_s;   // staging: [128][2] (m, l) from wk=1

    if (wk == 1) {
#pragma unroll
        for (int mt = 0; mt < 2; mt++) {
            int rA = mw + mt * 16 + g, rB = rA + 8;
            if (t == 0) {
                mst[rA * 2] = m_st[mt][0]; mst[rA * 2 + 1] = l_st[mt][0];
                mst[rB * 2] = m_st[mt][1]; mst[rB * 2 + 1] = l_st[mt][1];
            }
#pragma unroll
            for (int nt = 0; nt < 8; nt++) {
                int col = nt * 8 + 2 * t;
                *(float2*)&ost[rA * ASTR + col] = make_float2(o[mt][nt][0], o[mt][nt][1]);
                *(float2*)&ost[rB * ASTR + col] = make_float2(o[mt][nt][2], o[mt][nt][3]);
            }
        }
    }
    __syncthreads();

    if (wk == 0) {
        float snk = sinks[h];
#pragma unroll
        for (int mt = 0; mt < 2; mt++) {
            int rA = mw + mt * 16 + g, rB = rA + 8;
            float m1A = mst[rA * 2], l1A = mst[rA * 2 + 1];
            float m1B = mst[rB * 2], l1B = mst[rB * 2 + 1];
            float m0A = m_st[mt][0], l0A = l_st[mt][0];
            float m0B = m_st[mt][1], l0B = l_st[mt][1];

            float mfA = fmaxf(m0A, m1A);
            float c0A = __expf(m0A - mfA), c1A = __expf(m1A - mfA);
            float lfA = l0A * c0A + l1A * c1A;
            float lseA = mfA + logf(lfA);
            float sA = (1.f / (1.f + __expf(-(lseA - snk)))) / lfA;

            float mfB = fmaxf(m0B, m1B);
            float c0B = __expf(m0B - mfB), c1B = __expf(m1B - mfB);
            float lfB = l0B * c0B + l1B * c1B;
            float lseB = mfB + logf(lfB);
            float sB = (1.f / (1.f + __expf(-(lseB - snk)))) / lfB;

#pragma unroll
            for (int nt = 0; nt < 8; nt++) {
                int col = nt * 8 + 2 * t;
                float2 p1A = *(float2*)&ost[rA * ASTR + col];
                float2 p1B = *(float2*)&ost[rB * ASTR + col];
                float2 fa = make_float2((o[mt][nt][0] * c0A + p1A.x * c1A) * sA,
                                        (o[mt][nt][1] * c0A + p1A.y * c1A) * sA);
                float2 fb = make_float2((o[mt][nt][2] * c0B + p1B.x * c1B) * sB,
                                        (o[mt][nt][3] * c0B + p1B.y * c1B) * sB);
                *(float2*)&O[(q0 + rA) * (NH * HD) + h * HD + col] = fa;
                *(float2*)&O[(q0 + rB) * (NH * HD) + h * HD + col] = fb;
            }
        }
    }
}

#define ATT_SMEM ((128 * ASTR + 128 * ASTR + 64 * VSTR + 128 * VSTR) * (int)sizeof(unsigned))

// ---------------- launch ----------------------------------------------------
extern "C" void kernel_launch(void* const* d_in, const int* in_sizes, int n_in,
                              void* d_out, int out_size)
{
    const float* x     = (const float*)d_in[0];
    const float* rope  = (const float*)d_in[1];
    const float* wq_w  = (const float*)d_in[2];
    const float* wq_b  = (const float*)d_in[3];
    const float* wk_w  = (const float*)d_in[4];
    const float* wk_b  = (const float*)d_in[5];
    const float* wv_w  = (const float*)d_in[6];
    const float* wv_b  = (const float*)d_in[7];
    const float* wo_w  = (const float*)d_in[8];
    const float* wo_b  = (const float*)d_in[9];
    const float* sinks = (const float*)d_in[10];
    float* out = (float*)d_out;

    float *gq, *gk, *gv, *ga;
    cudaGetSymbolAddress((void**)&gq, g_q);
    cudaGetSymbolAddress((void**)&gk, g_k);
    cudaGetSymbolAddress((void**)&gv, g_v);
    cudaGetSymbolAddress((void**)&ga, g_attn);

    cudaFuncSetAttribute(qkv_gemm, cudaFuncAttributeMaxDynamicSharedMemorySize,
                         GEMM_SMEM);
    cudaFuncSetAttribute(gemm2, cudaFuncAttributeMaxDynamicSharedMemorySize,
                         GEMM_SMEM);
    cudaFuncSetAttribute(attn_mma, cudaFuncAttributeMaxDynamicSharedMemorySize,
                         ATT_SMEM);

    // Fused QKV projections
    qkv_gemm<<<dim3(24, 16), 256, GEMM_SMEM>>>(x, wq_w, wq_b, gq,
                                               wk_w, wk_b, gk,
                                               wv_w, wv_b, gv);

    // RoPE on Q and K
    {
        int tq = S_LEN * NH * (HD / 2);
        rope_kernel<<<(tq + 255) / 256, 256>>>(gq, rope, NH);
        int tk = S_LEN * NKV * (HD / 2);
        rope_kernel<<<(tk + 255) / 256, 256>>>(gk, rope, NKV);
    }

    // Flash attention (split-KV, 8 warps)
    attn_mma<<<dim3(S_LEN / ATT_BQ, NH), 256, ATT_SMEM>>>(gq, gk, gv, sinks, ga);

    // Output projection
    gemm2<<<dim3(16, 16), 256, GEMM_SMEM>>>(ga, wo_w, wo_b, out, DIM, NH * HD);
}